// round 8
// baseline (speedup 1.0000x reference)
#include <cuda_runtime.h>
#include <cuda_bf16.h>
#include <cstdint>
#include <math.h>

// Problem constants
#define BATCH 16
#define C 256
#define HW 1024          // 32x32
#define HEADS 8
#define HDIM 32
#define M_TOTAL (BATCH * HW)   // 16384
#define KCONV (C * 9)          // 2304

// ---------------- scratch (static device globals; no runtime allocation) ---------
__device__ float g_w1t[KCONV * C];    // [r][c][n] bn1-folded conv1 weights (tf32)
__device__ float g_w2t[KCONV * C];
__device__ float g_b1[C];
__device__ float g_b2[C];
__device__ float g_wqkv[C * 768];     // [K=256][N=768] (q|k|v transposed, tf32)
__device__ float g_bqkv[768];
__device__ float g_wot[C * C];        // out_w transposed (tf32)
__device__ float g_t1[BATCH * C * HW];
__device__ float g_conv[BATCH * C * HW];
__device__ float g_qkv[BATCH * 768 * HW];
__device__ float g_attn[BATCH * C * HW];
// shifted copies: S_m1[q] = in[q-1], S_p1[q] = in[q+1], x-row-edge zeros
__device__ float g_xm1[BATCH * C * HW];
__device__ float g_xp1[BATCH * C * HW];
__device__ float g_t1m[BATCH * C * HW];   // edge cells never written -> stay 0
__device__ float g_t1p[BATCH * C * HW];

// ---------------- helpers ----------------
__device__ __forceinline__ float to_tf32(float x) {
    float y;
    asm("cvt.rna.tf32.f32 %0, %1;" : "=f"(y) : "f"(x));
    return y;
}

__device__ __forceinline__ void mma_tf32(float* c, const unsigned* a, const unsigned* b) {
    asm volatile(
        "mma.sync.aligned.m16n8k8.row.col.f32.tf32.tf32.f32 "
        "{%0,%1,%2,%3}, {%4,%5,%6,%7}, {%8,%9}, {%0,%1,%2,%3};\n"
        : "+f"(c[0]), "+f"(c[1]), "+f"(c[2]), "+f"(c[3])
        : "r"(a[0]), "r"(a[1]), "r"(a[2]), "r"(a[3]), "r"(b[0]), "r"(b[1]));
}

__device__ __forceinline__ void cp16(uint32_t s, const void* g) {
    asm volatile("cp.async.cg.shared.global [%0], [%1], 16;" :: "r"(s), "l"(g));
}
__device__ __forceinline__ void cp16_pred(uint32_t s, const void* g, bool ok) {
    int sz = ok ? 16 : 0;
    asm volatile("cp.async.cg.shared.global [%0], [%1], 16, %2;" :: "r"(s), "l"(g), "r"(sz));
}
__device__ __forceinline__ void cp_commit() { asm volatile("cp.async.commit_group;"); }
template<int N> __device__ __forceinline__ void cp_wait() {
    asm volatile("cp.async.wait_group %0;" :: "n"(N));
}

// fast exp on the FMA pipe. x <= 0 expected.
__device__ __forceinline__ float fast_exp(float x) {
    float t = x * 1.4426950408889634f;
    t = fmaxf(t, -126.0f);
    float fi = floorf(t);
    float f = t - fi;
    float p = fmaf(f, 0.0015041f, 0.0096181f);
    p = fmaf(f, p, 0.0555041f);
    p = fmaf(f, p, 0.2402265f);
    p = fmaf(f, p, 0.6931472f);
    p = fmaf(f, p, 1.0f);
    int e = (int)fi;
    return p * __int_as_float((e + 127) << 23);
}

// ---------------- x shift kernel ----------------
__global__ void xshift_kernel(const float* __restrict__ in,
                              float* __restrict__ om1, float* __restrict__ op1)
{
    int i = blockIdx.x * blockDim.x + threadIdx.x;
    if (i >= BATCH * C * HW) return;
    int col = i & 31;
    om1[i] = (col > 0)  ? in[i - 1] : 0.f;   // S_m1[q] = in[q-1]
    op1[i] = (col < 31) ? in[i + 1] : 0.f;   // S_p1[q] = in[q+1]
}

// ---------------- weight transform + BN fold ----------------
__global__ void prep_kernel(
    const float* __restrict__ conv1_w, const float* __restrict__ conv1_b,
    const float* __restrict__ g1, const float* __restrict__ be1,
    const float* __restrict__ m1, const float* __restrict__ v1,
    const float* __restrict__ conv2_w, const float* __restrict__ conv2_b,
    const float* __restrict__ g2, const float* __restrict__ be2,
    const float* __restrict__ m2, const float* __restrict__ v2,
    const float* __restrict__ q_w, const float* __restrict__ q_b,
    const float* __restrict__ k_w, const float* __restrict__ k_b,
    const float* __restrict__ v_w, const float* __restrict__ v_b,
    const float* __restrict__ o_w)
{
    const int W1T_N = KCONV * C;          // 589824
    const int QKV_N = C * 768;            // 196608
    const int WOT_N = C * C;              // 65536
    const int total = 2 * W1T_N + QKV_N + WOT_N + 768 + 512;
    for (int i = blockIdx.x * blockDim.x + threadIdx.x; i < total;
         i += gridDim.x * blockDim.x) {
        if (i < W1T_N) {
            int k = i >> 8, o = i & 255;       // k = r*256 + c
            int r = k >> 8, c = k & 255;
            float s = g1[o] * rsqrtf(v1[o] + 1e-5f);
            g_w1t[i] = to_tf32(conv1_w[(o * C + c) * 9 + r] * s);
        } else if (i < 2 * W1T_N) {
            int j = i - W1T_N;
            int k = j >> 8, o = j & 255;
            int r = k >> 8, c = k & 255;
            float s = g2[o] * rsqrtf(v2[o] + 1e-5f);
            g_w2t[j] = to_tf32(conv2_w[(o * C + c) * 9 + r] * s);
        } else if (i < 2 * W1T_N + QKV_N) {
            int j = i - 2 * W1T_N;
            int c = j / 768, n = j - c * 768;
            float w;
            if (n < 256)      w = q_w[n * C + c];
            else if (n < 512) w = k_w[(n - 256) * C + c];
            else              w = v_w[(n - 512) * C + c];
            g_wqkv[j] = to_tf32(w);
        } else if (i < 2 * W1T_N + QKV_N + WOT_N) {
            int j = i - (2 * W1T_N + QKV_N);
            int c = j >> 8, o = j & 255;
            g_wot[j] = to_tf32(o_w[o * C + c]);
        } else if (i < 2 * W1T_N + QKV_N + WOT_N + 768) {
            int n = i - (2 * W1T_N + QKV_N + WOT_N);
            float bb;
            if (n < 256)      bb = q_b[n];
            else if (n < 512) bb = k_b[n - 256];
            else              bb = v_b[n - 512];
            g_bqkv[n] = bb;
        } else {
            int j = i - (2 * W1T_N + QKV_N + WOT_N + 768); // 0..511
            int o = j & 255;
            if (j < 256) {
                float s = g1[o] * rsqrtf(v1[o] + 1e-5f);
                g_b1[o] = conv1_b[o] * s + be1[o] - m1[o] * s;
            } else {
                float s = g2[o] * rsqrtf(v2[o] + 1e-5f);
                g_b2[o] = conv2_b[o] * s + be2[o] - m2[o] * s;
            }
        }
    }
}

// ---------------- common tile params ----------------
#define BM 128
#define BN 128
#define BKT 16
#define AMS 136   // 136 % 32 = 8 -> conflict-free fragment LDS
#define STAGE_F (BKT * AMS)   // floats per stage per matrix = 2176
#define GEMM_SMEM ((3 * STAGE_F * 2) * 4)

// ---------------- 1x1 TF32 GEMM (qkv / out-proj), 3-stage cp.async ----------------
// EPI 0: out = acc + bias
// EPI 2: out = relu(conv + sigmoid(gate)*(acc + bias) + resid)
template<int EPI, int ROUND>
__global__ void __launch_bounds__(256, 2) gemm_k(
    const float* __restrict__ A, const float* __restrict__ Bw,
    const float* __restrict__ bias, float* __restrict__ Cout,
    int Kdim, int Ndim,
    const float* __restrict__ convres, const float* __restrict__ resid,
    const float* __restrict__ gp)
{
    extern __shared__ float dyn[];
    float* sA = dyn;
    float* sB = dyn + 3 * STAGE_F;

    const int tid  = threadIdx.x;
    const int lane = tid & 31;
    const int wid  = tid >> 5;
    const int wm   = wid & 1;
    const int wn   = wid >> 1;
    const int m0 = blockIdx.x * BM;
    const int n0 = blockIdx.y * BN;
    const int bq = m0 >> 10;
    const int p0 = m0 & 1023;

    const int sk  = tid >> 4;
    const int sm8 = (tid & 15) * 8;

    const uint32_t saA = (uint32_t)__cvta_generic_to_shared(sA);
    const uint32_t saB = (uint32_t)__cvta_generic_to_shared(sB);

    float acc[4][4][4];
#pragma unroll
    for (int i = 0; i < 4; i++)
#pragma unroll
        for (int j = 0; j < 4; j++)
#pragma unroll
            for (int q = 0; q < 4; q++) acc[i][j][q] = 0.f;

    const int nt = Kdim / BKT;

    auto stage = [&](int t, int st) {
        const int k = t * BKT + sk;
        uint32_t da = saA + (uint32_t)(st * STAGE_F + sk * AMS + sm8) * 4u;
        const float* ga = A + (((size_t)bq * C + k) << 10) + p0 + sm8;
        cp16(da, ga);
        cp16(da + 16, ga + 4);
        uint32_t db = saB + (uint32_t)(st * STAGE_F + sk * AMS + sm8) * 4u;
        const float* gb = Bw + (size_t)k * Ndim + n0 + sm8;
        cp16(db, gb);
        cp16(db + 16, gb + 4);
    };

    stage(0, 0); cp_commit();
    stage(1, 1); cp_commit();

    for (int t = 0; t < nt; t++) {
        const int cur = t % 3;
        cp_wait<1>();
        __syncthreads();
        if (t + 2 < nt) stage(t + 2, (t + 2) % 3);
        cp_commit();

        const float* fA = sA + cur * STAGE_F;
        const float* fB = sB + cur * STAGE_F;
#pragma unroll
        for (int ks = 0; ks < 2; ks++) {
            const int kc = ks * 8 + (lane & 3);
            unsigned af[4][4], bf[4][2];
#pragma unroll
            for (int mi = 0; mi < 4; mi++) {
                int ar = wm * 64 + mi * 16 + (lane >> 2);
                af[mi][0] = __float_as_uint(fA[kc * AMS + ar]);
                af[mi][1] = __float_as_uint(fA[kc * AMS + ar + 8]);
                af[mi][2] = __float_as_uint(fA[(kc + 4) * AMS + ar]);
                af[mi][3] = __float_as_uint(fA[(kc + 4) * AMS + ar + 8]);
            }
#pragma unroll
            for (int nj = 0; nj < 4; nj++) {
                int br = wn * 32 + nj * 8 + (lane >> 2);
                bf[nj][0] = __float_as_uint(fB[kc * AMS + br]);
                bf[nj][1] = __float_as_uint(fB[(kc + 4) * AMS + br]);
            }
#pragma unroll
            for (int mi = 0; mi < 4; mi++)
#pragma unroll
                for (int nj = 0; nj < 4; nj++)
                    mma_tf32(acc[mi][nj], af[mi], bf[nj]);
        }
    }

    float sg = 0.f;
    if (EPI == 2) sg = 1.f / (1.f + __expf(-gp[0]));
#pragma unroll
    for (int mi = 0; mi < 4; mi++) {
#pragma unroll
        for (int half = 0; half < 2; half++) {
            int m = m0 + wm * 64 + mi * 16 + (lane >> 2) + half * 8;
            int mb = m >> 10, p = m & 1023;
#pragma unroll
            for (int nj = 0; nj < 4; nj++) {
                int n = n0 + wn * 32 + nj * 8 + 2 * (lane & 3);
                float v0 = acc[mi][nj][half * 2 + 0] + bias[n];
                float v1 = acc[mi][nj][half * 2 + 1] + bias[n + 1];
                size_t addr = (((size_t)mb * Ndim + n) << 10) + p;
                if (EPI == 2) {
                    float c0 = convres[addr], c1 = convres[addr + 1024];
                    float r0 = resid[addr],   r1 = resid[addr + 1024];
                    v0 = fmaxf(c0 + sg * v0 + r0, 0.f);
                    v1 = fmaxf(c1 + sg * v1 + r1, 0.f);
                }
                if (ROUND) { v0 = to_tf32(v0); v1 = to_tf32(v1); }
                Cout[addr]        = v0;
                Cout[addr + 1024] = v1;
            }
        }
    }
}

// ---------------- conv3x3 via pre-shifted inputs: clean GEMM mainloop ------------
// A0/Am1/Ap1: dx = 0/-1/+1 copies (Am1[q]=in[q-1], Ap1[q]=in[q+1]).
// Weights [r*256+c][n], r = (dy+1)*3 + (dx+1).
// EPI 1: relu(acc+bias)   EPI 0: acc+bias
// SHIFT: also emit S_m1/S_p1 copies of the output (for next conv)
template<int EPI, int ROUND, int SHIFT>
__global__ void __launch_bounds__(256, 2) convgemm_k(
    const float* __restrict__ A0, const float* __restrict__ Am1,
    const float* __restrict__ Ap1,
    const float* __restrict__ Bw, const float* __restrict__ bias,
    float* __restrict__ Cout, float* __restrict__ Cm1, float* __restrict__ Cp1)
{
    extern __shared__ float dyn[];
    float* sA = dyn;
    float* sB = dyn + 3 * STAGE_F;

    const int tid  = threadIdx.x;
    const int lane = tid & 31;
    const int wid  = tid >> 5;
    const int wm   = wid & 1;
    const int wn   = wid >> 1;
    const int m0 = blockIdx.x * BM;
    const int n0 = blockIdx.y * BN;
    const int bq = m0 >> 10;
    const int p0 = m0 & 1023;

    const int sk  = tid >> 4;        // channel within 16-tile
    const int sm8 = (tid & 15) * 8;

    const uint32_t saA = (uint32_t)__cvta_generic_to_shared(sA);
    const uint32_t saB = (uint32_t)__cvta_generic_to_shared(sB);

    float acc[4][4][4];
#pragma unroll
    for (int i = 0; i < 4; i++)
#pragma unroll
        for (int j = 0; j < 4; j++)
#pragma unroll
            for (int q = 0; q < 4; q++) acc[i][j][q] = 0.f;

    const int nt = 144;   // 9 taps * 16 channel-tiles

    auto stage = [&](int t, int st) {
        const int r   = t >> 4;          // tap 0..8
        const int ct  = t & 15;          // channel tile
        const int dy  = r / 3 - 1;
        const int dxi = r % 3;           // 0: dx=-1 -> Am1   1: dx=0 -> A0   2: dx=+1 -> Ap1
        const float* Ab = (dxi == 0) ? Am1 : (dxi == 1) ? A0 : Ap1;
        const int c  = ct * 16 + sk;
        uint32_t da = saA + (uint32_t)(st * STAGE_F + sk * AMS + sm8) * 4u;
        int y = ((p0 + sm8) >> 5) + dy;
        bool ok = ((unsigned)y < 32u);
        const float* ga = ok ? (Ab + (((size_t)bq * C + c) << 10) + p0 + dy * 32 + sm8) : A0;
        cp16_pred(da, ga, ok);
        cp16_pred(da + 16, ga + 4, ok);
        uint32_t db = saB + (uint32_t)(st * STAGE_F + sk * AMS + sm8) * 4u;
        const float* gb = Bw + (size_t)(t * BKT + sk) * C + n0 + sm8;
        cp16(db, gb);
        cp16(db + 16, gb + 4);
    };

    stage(0, 0); cp_commit();
    stage(1, 1); cp_commit();

    for (int t = 0; t < nt; t++) {
        const int cur = t % 3;
        cp_wait<1>();
        __syncthreads();
        if (t + 2 < nt) stage(t + 2, (t + 2) % 3);
        cp_commit();

        const float* fA = sA + cur * STAGE_F;
        const float* fB = sB + cur * STAGE_F;
#pragma unroll
        for (int ks = 0; ks < 2; ks++) {
            const int kc = ks * 8 + (lane & 3);
            unsigned af[4][4], bf[4][2];
#pragma unroll
            for (int mi = 0; mi < 4; mi++) {
                int ar = wm * 64 + mi * 16 + (lane >> 2);
                af[mi][0] = __float_as_uint(fA[kc * AMS + ar]);
                af[mi][1] = __float_as_uint(fA[kc * AMS + ar + 8]);
                af[mi][2] = __float_as_uint(fA[(kc + 4) * AMS + ar]);
                af[mi][3] = __float_as_uint(fA[(kc + 4) * AMS + ar + 8]);
            }
#pragma unroll
            for (int nj = 0; nj < 4; nj++) {
                int br = wn * 32 + nj * 8 + (lane >> 2);
                bf[nj][0] = __float_as_uint(fB[kc * AMS + br]);
                bf[nj][1] = __float_as_uint(fB[(kc + 4) * AMS + br]);
            }
#pragma unroll
            for (int mi = 0; mi < 4; mi++)
#pragma unroll
                for (int nj = 0; nj < 4; nj++)
                    mma_tf32(acc[mi][nj], af[mi], bf[nj]);
        }
    }

#pragma unroll
    for (int mi = 0; mi < 4; mi++) {
#pragma unroll
        for (int half = 0; half < 2; half++) {
            int m = m0 + wm * 64 + mi * 16 + (lane >> 2) + half * 8;
            int mb = m >> 10, p = m & 1023;
            int xcol = p & 31;
#pragma unroll
            for (int nj = 0; nj < 4; nj++) {
                int n = n0 + wn * 32 + nj * 8 + 2 * (lane & 3);
                float v0 = acc[mi][nj][half * 2 + 0] + bias[n];
                float v1 = acc[mi][nj][half * 2 + 1] + bias[n + 1];
                size_t addr = (((size_t)mb * C + n) << 10) + p;
                if (EPI == 1) { v0 = fmaxf(v0, 0.f); v1 = fmaxf(v1, 0.f); }
                if (ROUND) { v0 = to_tf32(v0); v1 = to_tf32(v1); }
                Cout[addr]        = v0;
                Cout[addr + 1024] = v1;
                if (SHIFT) {
                    // Cm1[q] = out[q-1]: write out[p] to Cm1[p+1] (col<31)
                    // Cp1[q] = out[q+1]: write out[p] to Cp1[p-1] (col>0)
                    if (xcol < 31) { Cm1[addr + 1] = v0; Cm1[addr + 1024 + 1] = v1; }
                    if (xcol > 0)  { Cp1[addr - 1] = v0; Cp1[addr + 1024 - 1] = v1; }
                }
            }
        }
    }
}

// ---------------- attention kernel (TF32 mma, 512 threads / 16 warps) ----------
#define SSTR 1044   // 1044 % 32 = 20 -> conflict-free P-frag loads
#define QS2 36      // sQ [d][q]
#define KS2 132     // sK [d][key]
#define VSTR 132    // sV [d][key]

__global__ void __launch_bounds__(512, 1) attn_kernel(
    const float* __restrict__ qkv, float* __restrict__ out)
{
    extern __shared__ float sm[];
    float* sS   = sm;                    // [32][SSTR]
    float* sQ   = sS + 32 * SSTR;        // [32 d][QS2]
    float* sK   = sQ + 32 * QS2;         // [32 d][KS2]
    float* sV   = sK + 32 * KS2;         // [32 d][VSTR]
    float* sO   = sV + 32 * VSTR;        // [8][32][33]
    float* sInv = sO + 8 * 32 * 33;      // [32]

    const int tid  = threadIdx.x;
    const int lane = tid & 31;
    const int w    = tid >> 5;           // 0..15
    const int n0 = blockIdx.x * 32;
    const int h  = blockIdx.y;
    const int b  = blockIdx.z;

    const float* qbase = qkv + ((size_t)b * 768 + h * HDIM) * HW;
    const float* kbase = qbase + 256 * HW;
    const float* vbase = qbase + 512 * HW;
    const float scale = 0.17677669529663687f;  // 1/sqrt(32)

    if (tid < 256) {
        int d = tid >> 3, q4 = (tid & 7) * 4;
        *(float4*)&sQ[d * QS2 + q4] = *(const float4*)&qbase[d * HW + n0 + q4];
    }
    __syncthreads();

    unsigned aq[2][4][4];
#pragma unroll
    for (int mi = 0; mi < 2; mi++)
#pragma unroll
        for (int ks = 0; ks < 4; ks++) {
            int qr = mi * 16 + (lane >> 2);
            int dc = ks * 8 + (lane & 3);
            aq[mi][ks][0] = __float_as_uint(sQ[dc * QS2 + qr]);
            aq[mi][ks][1] = __float_as_uint(sQ[dc * QS2 + qr + 8]);
            aq[mi][ks][2] = __float_as_uint(sQ[(dc + 4) * QS2 + qr]);
            aq[mi][ks][3] = __float_as_uint(sQ[(dc + 4) * QS2 + qr + 8]);
        }

    for (int kt = 0; kt < 8; kt++) {
        __syncthreads();
        for (int i = tid; i < 1024; i += 512) {
            int d = i >> 5, key4 = (i & 31) * 4;
            *(float4*)&sK[d * KS2 + key4] =
                *(const float4*)&kbase[d * HW + kt * 128 + key4];
        }
        __syncthreads();

        float cS[2][4];
#pragma unroll
        for (int mi = 0; mi < 2; mi++)
#pragma unroll
            for (int q = 0; q < 4; q++) cS[mi][q] = 0.f;

#pragma unroll
        for (int ks = 0; ks < 4; ks++) {
            int dc = ks * 8 + (lane & 3);
            int ncol = w * 8 + (lane >> 2);
            unsigned bf[2];
            bf[0] = __float_as_uint(sK[dc * KS2 + ncol]);
            bf[1] = __float_as_uint(sK[(dc + 4) * KS2 + ncol]);
#pragma unroll
            for (int mi = 0; mi < 2; mi++)
                mma_tf32(cS[mi], aq[mi][ks], bf);
        }
#pragma unroll
        for (int mi = 0; mi < 2; mi++) {
            int qr = mi * 16 + (lane >> 2);
            int kc = kt * 128 + w * 8 + 2 * (lane & 3);
            sS[qr * SSTR + kc]           = cS[mi][0] * scale;
            sS[qr * SSTR + kc + 1]       = cS[mi][1] * scale;
            sS[(qr + 8) * SSTR + kc]     = cS[mi][2] * scale;
            sS[(qr + 8) * SSTR + kc + 1] = cS[mi][3] * scale;
        }
    }
    __syncthreads();

#pragma unroll
    for (int r = 0; r < 2; r++) {
        int q = w * 2 + r;
        float* row = sS + q * SSTR;
        float mx = -1e30f;
        for (int m = lane; m < 1024; m += 32) mx = fmaxf(mx, row[m]);
#pragma unroll
        for (int off = 16; off; off >>= 1)
            mx = fmaxf(mx, __shfl_xor_sync(0xffffffffu, mx, off));
        float s = 0.f;
        for (int m = lane; m < 1024; m += 32) {
            float e = fast_exp(row[m] - mx);
            row[m] = e;
            s += e;
        }
#pragma unroll
        for (int off = 16; off; off >>= 1)
            s += __shfl_xor_sync(0xffffffffu, s, off);
        if (lane == 0) sInv[q] = 1.f / s;
    }

    float cO[2][4][4];
#pragma unroll
    for (int mi = 0; mi < 2; mi++)
#pragma unroll
        for (int nd = 0; nd < 4; nd++)
#pragma unroll
            for (int q = 0; q < 4; q++) cO[mi][nd][q] = 0.f;

    for (int kt = 0; kt < 8; kt++) {
        __syncthreads();
        for (int i = tid; i < 1024; i += 512) {
            int d = i >> 5, key4 = (i & 31) * 4;
            *(float4*)&sV[d * VSTR + key4] =
                *(const float4*)&vbase[d * HW + kt * 128 + key4];
        }
        __syncthreads();

        int kc = w * 8 + (lane & 3);
        int col = kt * 128 + kc;
        unsigned af[2][4];
#pragma unroll
        for (int mi = 0; mi < 2; mi++) {
            int qr = mi * 16 + (lane >> 2);
            af[mi][0] = __float_as_uint(sS[qr * SSTR + col]);
            af[mi][1] = __float_as_uint(sS[(qr + 8) * SSTR + col]);
            af[mi][2] = __float_as_uint(sS[qr * SSTR + col + 4]);
            af[mi][3] = __float_as_uint(sS[(qr + 8) * SSTR + col + 4]);
        }
#pragma unroll
        for (int nd = 0; nd < 4; nd++) {
            int dc = nd * 8 + (lane >> 2);
            unsigned bf[2];
            bf[0] = __float_as_uint(sV[dc * VSTR + kc]);
            bf[1] = __float_as_uint(sV[dc * VSTR + kc + 4]);
#pragma unroll
            for (int mi = 0; mi < 2; mi++)
                mma_tf32(cO[mi][nd], af[mi], bf);
        }
    }

    if (w >= 8) {
#pragma unroll
        for (int mi = 0; mi < 2; mi++)
#pragma unroll
            for (int nd = 0; nd < 4; nd++) {
                int q = mi * 16 + (lane >> 2);
                int d = nd * 8 + 2 * (lane & 3);
                int base = ((w - 8) * 32 + q) * 33 + d;
                sO[base]            = cO[mi][nd][0];
                sO[base + 1]        = cO[mi][nd][1];
                sO[base + 8 * 33]   = cO[mi][nd][2];
                sO[base + 8 * 33 + 1] = cO[mi][nd][3];
            }
    }
    __syncthreads();
    if (w < 8) {
#pragma unroll
        for (int mi = 0; mi < 2; mi++)
#pragma unroll
            for (int nd = 0; nd < 4; nd++) {
                int q = mi * 16 + (lane >> 2);
                int d = nd * 8 + 2 * (lane & 3);
                int base = (w * 32 + q) * 33 + d;
                sO[base]              = cO[mi][nd][0] + sO[base];
                sO[base + 1]          = cO[mi][nd][1] + sO[base + 1];
                sO[base + 8 * 33]     = cO[mi][nd][2] + sO[base + 8 * 33];
                sO[base + 8 * 33 + 1] = cO[mi][nd][3] + sO[base + 8 * 33 + 1];
            }
    }
    __syncthreads();

    for (int i = tid; i < 1024; i += 512) {
        int q = i & 31, d = i >> 5;
        float s = 0.f;
#pragma unroll
        for (int ww = 0; ww < 8; ww++)
            s += sO[(ww * 32 + q) * 33 + d];
        out[((size_t)b * C + h * HDIM + d) * HW + n0 + q] = to_tf32(s * sInv[q]);
    }
}

// ---------------- launch ----------------
extern "C" void kernel_launch(void* const* d_in, const int* in_sizes, int n_in,
                              void* d_out, int out_size)
{
    const float* x       = (const float*)d_in[0];
    const float* conv1_w = (const float*)d_in[1];
    const float* conv1_b = (const float*)d_in[2];
    const float* bn1_g   = (const float*)d_in[3];
    const float* bn1_b   = (const float*)d_in[4];
    const float* bn1_m   = (const float*)d_in[5];
    const float* bn1_v   = (const float*)d_in[6];
    const float* conv2_w = (const float*)d_in[7];
    const float* conv2_b = (const float*)d_in[8];
    const float* bn2_g   = (const float*)d_in[9];
    const float* bn2_b   = (const float*)d_in[10];
    const float* bn2_m   = (const float*)d_in[11];
    const float* bn2_v   = (const float*)d_in[12];
    const float* q_w     = (const float*)d_in[13];
    const float* q_b     = (const float*)d_in[14];
    const float* k_w     = (const float*)d_in[15];
    const float* k_b     = (const float*)d_in[16];
    const float* v_w     = (const float*)d_in[17];
    const float* v_b     = (const float*)d_in[18];
    const float* o_w     = (const float*)d_in[19];
    const float* o_b     = (const float*)d_in[20];
    const float* gate    = (const float*)d_in[21];
    float* out           = (float*)d_out;

    float *p_w1t, *p_w2t, *p_b1, *p_b2, *p_wqkv, *p_bqkv, *p_wot;
    float *p_t1, *p_conv, *p_qkv, *p_attn;
    float *p_xm1, *p_xp1, *p_t1m, *p_t1p;
    cudaGetSymbolAddress((void**)&p_w1t,  g_w1t);
    cudaGetSymbolAddress((void**)&p_w2t,  g_w2t);
    cudaGetSymbolAddress((void**)&p_b1,   g_b1);
    cudaGetSymbolAddress((void**)&p_b2,   g_b2);
    cudaGetSymbolAddress((void**)&p_wqkv, g_wqkv);
    cudaGetSymbolAddress((void**)&p_bqkv, g_bqkv);
    cudaGetSymbolAddress((void**)&p_wot,  g_wot);
    cudaGetSymbolAddress((void**)&p_t1,   g_t1);
    cudaGetSymbolAddress((void**)&p_conv, g_conv);
    cudaGetSymbolAddress((void**)&p_qkv,  g_qkv);
    cudaGetSymbolAddress((void**)&p_attn, g_attn);
    cudaGetSymbolAddress((void**)&p_xm1,  g_xm1);
    cudaGetSymbolAddress((void**)&p_xp1,  g_xp1);
    cudaGetSymbolAddress((void**)&p_t1m,  g_t1m);
    cudaGetSymbolAddress((void**)&p_t1p,  g_t1p);

    static cudaStream_t s_side = nullptr;
    static cudaEvent_t ev_fork = nullptr, ev_join = nullptr;
    static bool attrs_set = false;
    if (s_side == nullptr) {
        cudaStreamCreateWithFlags(&s_side, cudaStreamNonBlocking);
        cudaEventCreateWithFlags(&ev_fork, cudaEventDisableTiming);
        cudaEventCreateWithFlags(&ev_join, cudaEventDisableTiming);
    }
    const int attn_smem = (32 * SSTR + 32 * QS2 + 32 * KS2 + 32 * VSTR
                           + 8 * 32 * 33 + 32) * (int)sizeof(float);
    if (!attrs_set) {
        cudaFuncSetAttribute(gemm_k<0, 1>, cudaFuncAttributeMaxDynamicSharedMemorySize, GEMM_SMEM);
        cudaFuncSetAttribute(gemm_k<2, 0>, cudaFuncAttributeMaxDynamicSharedMemorySize, GEMM_SMEM);
        cudaFuncSetAttribute(convgemm_k<1, 1, 1>, cudaFuncAttributeMaxDynamicSharedMemorySize, GEMM_SMEM);
        cudaFuncSetAttribute(convgemm_k<0, 0, 0>, cudaFuncAttributeMaxDynamicSharedMemorySize, GEMM_SMEM);
        cudaFuncSetAttribute(attn_kernel, cudaFuncAttributeMaxDynamicSharedMemorySize, attn_smem);
        attrs_set = true;
    }

    // side stream: shifted copies of x (no dependencies)
    xshift_kernel<<<(BATCH * C * HW) / 256, 256, 0, s_side>>>(x, p_xm1, p_xp1);

    // main: weight transform + BN fold
    prep_kernel<<<1024, 256>>>(conv1_w, conv1_b, bn1_g, bn1_b, bn1_m, bn1_v,
                               conv2_w, conv2_b, bn2_g, bn2_b, bn2_m, bn2_v,
                               q_w, q_b, k_w, k_b, v_w, v_b, o_w);

    // fork: conv chain on side stream (after prep)
    cudaEventRecord(ev_fork, 0);
    cudaStreamWaitEvent(s_side, ev_fork, 0);

    dim3 gConv(M_TOTAL / BM, C / BN);
    convgemm_k<1, 1, 1><<<gConv, 256, GEMM_SMEM, s_side>>>(
        x, p_xm1, p_xp1, p_w1t, p_b1, p_t1, p_t1m, p_t1p);
    convgemm_k<0, 0, 0><<<gConv, 256, GEMM_SMEM, s_side>>>(
        p_t1, p_t1m, p_t1p, p_w2t, p_b2, p_conv, nullptr, nullptr);
    cudaEventRecord(ev_join, s_side);

    // main stream: qkv -> attention
    dim3 gQKV(M_TOTAL / BM, 768 / BN);
    gemm_k<0, 1><<<gQKV, 256, GEMM_SMEM>>>(x, p_wqkv, p_bqkv, p_qkv, C, 768,
                                           nullptr, nullptr, nullptr);
    dim3 gAttn(HW / 32, HEADS, BATCH);
    attn_kernel<<<gAttn, 512, attn_smem>>>(p_qkv, p_attn);

    // join, then fused epilogue GEMM
    cudaStreamWaitEvent(0, ev_join, 0);
    dim3 gOut(M_TOTAL / BM, C / BN);
    gemm_k<2, 0><<<gOut, 256, GEMM_SMEM>>>(p_attn, p_wot, o_b, out, C, C,
                                           p_conv, x, gate);
}

// round 9
// speedup vs baseline: 1.6904x; 1.6904x over previous
#include <cuda_runtime.h>
#include <cuda_bf16.h>
#include <cstdint>
#include <math.h>

// Problem constants
#define BATCH 16
#define C 256
#define HW 1024          // 32x32
#define HEADS 8
#define HDIM 32
#define M_TOTAL (BATCH * HW)   // 16384
#define KCONV (C * 9)          // 2304

// ---------------- scratch (static device globals; no runtime allocation) ---------
__device__ float g_w1t[KCONV * C];    // [r][c][n] bn1-folded conv1 weights (tf32)
__device__ float g_w2t[KCONV * C];
__device__ float g_b1[C];
__device__ float g_b2[C];
__device__ float g_wqkv[C * 768];     // [K=256][N=768] (q|k|v transposed, tf32)
__device__ float g_bqkv[768];
__device__ float g_wot[C * C];        // out_w transposed (tf32)
__device__ float g_t1[BATCH * C * HW];
__device__ float g_conv[BATCH * C * HW];
__device__ float g_qkv[BATCH * 768 * HW];
__device__ float g_attn[BATCH * C * HW];
// shifted copies: S_m1[q] = in[q-1], S_p1[q] = in[q+1], x-row-edge zeros
__device__ float g_xm1[BATCH * C * HW];
__device__ float g_xp1[BATCH * C * HW];
__device__ float g_t1m[BATCH * C * HW];   // edge cells never written -> stay 0
__device__ float g_t1p[BATCH * C * HW];

// ---------------- helpers ----------------
__device__ __forceinline__ float to_tf32(float x) {
    float y;
    asm("cvt.rna.tf32.f32 %0, %1;" : "=f"(y) : "f"(x));
    return y;
}

__device__ __forceinline__ void mma_tf32(float* c, const unsigned* a, const unsigned* b) {
    asm volatile(
        "mma.sync.aligned.m16n8k8.row.col.f32.tf32.tf32.f32 "
        "{%0,%1,%2,%3}, {%4,%5,%6,%7}, {%8,%9}, {%0,%1,%2,%3};\n"
        : "+f"(c[0]), "+f"(c[1]), "+f"(c[2]), "+f"(c[3])
        : "r"(a[0]), "r"(a[1]), "r"(a[2]), "r"(a[3]), "r"(b[0]), "r"(b[1]));
}

__device__ __forceinline__ void cp16(uint32_t s, const void* g) {
    asm volatile("cp.async.cg.shared.global [%0], [%1], 16;" :: "r"(s), "l"(g));
}
__device__ __forceinline__ void cp16_pred(uint32_t s, const void* g, bool ok) {
    int sz = ok ? 16 : 0;
    asm volatile("cp.async.cg.shared.global [%0], [%1], 16, %2;" :: "r"(s), "l"(g), "r"(sz));
}
__device__ __forceinline__ void cp_commit() { asm volatile("cp.async.commit_group;"); }
template<int N> __device__ __forceinline__ void cp_wait() {
    asm volatile("cp.async.wait_group %0;" :: "n"(N));
}

// fast exp on the FMA pipe. x <= 0 expected.
__device__ __forceinline__ float fast_exp(float x) {
    float t = x * 1.4426950408889634f;
    t = fmaxf(t, -126.0f);
    float fi = floorf(t);
    float f = t - fi;
    float p = fmaf(f, 0.0015041f, 0.0096181f);
    p = fmaf(f, p, 0.0555041f);
    p = fmaf(f, p, 0.2402265f);
    p = fmaf(f, p, 0.6931472f);
    p = fmaf(f, p, 1.0f);
    int e = (int)fi;
    return p * __int_as_float((e + 127) << 23);
}

// ---------------- x shift kernel ----------------
__global__ void xshift_kernel(const float* __restrict__ in,
                              float* __restrict__ om1, float* __restrict__ op1)
{
    int i = blockIdx.x * blockDim.x + threadIdx.x;
    if (i >= BATCH * C * HW) return;
    int col = i & 31;
    om1[i] = (col > 0)  ? in[i - 1] : 0.f;   // S_m1[q] = in[q-1]
    op1[i] = (col < 31) ? in[i + 1] : 0.f;   // S_p1[q] = in[q+1]
}

// ---------------- weight transform + BN fold ----------------
__global__ void prep_kernel(
    const float* __restrict__ conv1_w, const float* __restrict__ conv1_b,
    const float* __restrict__ g1, const float* __restrict__ be1,
    const float* __restrict__ m1, const float* __restrict__ v1,
    const float* __restrict__ conv2_w, const float* __restrict__ conv2_b,
    const float* __restrict__ g2, const float* __restrict__ be2,
    const float* __restrict__ m2, const float* __restrict__ v2,
    const float* __restrict__ q_w, const float* __restrict__ q_b,
    const float* __restrict__ k_w, const float* __restrict__ k_b,
    const float* __restrict__ v_w, const float* __restrict__ v_b,
    const float* __restrict__ o_w)
{
    const int W1T_N = KCONV * C;          // 589824
    const int QKV_N = C * 768;            // 196608
    const int WOT_N = C * C;              // 65536
    const int total = 2 * W1T_N + QKV_N + WOT_N + 768 + 512;
    for (int i = blockIdx.x * blockDim.x + threadIdx.x; i < total;
         i += gridDim.x * blockDim.x) {
        if (i < W1T_N) {
            int k = i >> 8, o = i & 255;       // k = r*256 + c
            int r = k >> 8, c = k & 255;
            float s = g1[o] * rsqrtf(v1[o] + 1e-5f);
            g_w1t[i] = to_tf32(conv1_w[(o * C + c) * 9 + r] * s);
        } else if (i < 2 * W1T_N) {
            int j = i - W1T_N;
            int k = j >> 8, o = j & 255;
            int r = k >> 8, c = k & 255;
            float s = g2[o] * rsqrtf(v2[o] + 1e-5f);
            g_w2t[j] = to_tf32(conv2_w[(o * C + c) * 9 + r] * s);
        } else if (i < 2 * W1T_N + QKV_N) {
            int j = i - 2 * W1T_N;
            int c = j / 768, n = j - c * 768;
            float w;
            if (n < 256)      w = q_w[n * C + c];
            else if (n < 512) w = k_w[(n - 256) * C + c];
            else              w = v_w[(n - 512) * C + c];
            g_wqkv[j] = to_tf32(w);
        } else if (i < 2 * W1T_N + QKV_N + WOT_N) {
            int j = i - (2 * W1T_N + QKV_N);
            int c = j >> 8, o = j & 255;
            g_wot[j] = to_tf32(o_w[o * C + c]);
        } else if (i < 2 * W1T_N + QKV_N + WOT_N + 768) {
            int n = i - (2 * W1T_N + QKV_N + WOT_N);
            float bb;
            if (n < 256)      bb = q_b[n];
            else if (n < 512) bb = k_b[n - 256];
            else              bb = v_b[n - 512];
            g_bqkv[n] = bb;
        } else {
            int j = i - (2 * W1T_N + QKV_N + WOT_N + 768); // 0..511
            int o = j & 255;
            if (j < 256) {
                float s = g1[o] * rsqrtf(v1[o] + 1e-5f);
                g_b1[o] = conv1_b[o] * s + be1[o] - m1[o] * s;
            } else {
                float s = g2[o] * rsqrtf(v2[o] + 1e-5f);
                g_b2[o] = conv2_b[o] * s + be2[o] - m2[o] * s;
            }
        }
    }
}

// ---------------- common tile params ----------------
#define BM 128
#define BN 128
#define BKT 16
#define AMS 136   // 136 % 32 = 8 -> conflict-free fragment LDS
#define STAGE_F (BKT * AMS)   // floats per stage per matrix = 2176
#define GEMM_SMEM ((3 * STAGE_F * 2) * 4)

// ---------------- 1x1 TF32 GEMM (qkv / out-proj), 3-stage cp.async ----------------
// EPI 0: out = acc + bias
// EPI 2: out = relu(conv + sigmoid(gate)*(acc + bias) + resid)
template<int EPI, int ROUND>
__global__ void __launch_bounds__(256, 2) gemm_k(
    const float* __restrict__ A, const float* __restrict__ Bw,
    const float* __restrict__ bias, float* __restrict__ Cout,
    int Kdim, int Ndim,
    const float* __restrict__ convres, const float* __restrict__ resid,
    const float* __restrict__ gp)
{
    extern __shared__ float dyn[];
    float* sA = dyn;
    float* sB = dyn + 3 * STAGE_F;

    const int tid  = threadIdx.x;
    const int lane = tid & 31;
    const int wid  = tid >> 5;
    const int wm   = wid & 1;
    const int wn   = wid >> 1;
    const int m0 = blockIdx.x * BM;
    const int n0 = blockIdx.y * BN;
    const int bq = m0 >> 10;
    const int p0 = m0 & 1023;

    const int sk  = tid >> 4;
    const int sm8 = (tid & 15) * 8;

    const uint32_t saA = (uint32_t)__cvta_generic_to_shared(sA);
    const uint32_t saB = (uint32_t)__cvta_generic_to_shared(sB);

    float acc[4][4][4];
#pragma unroll
    for (int i = 0; i < 4; i++)
#pragma unroll
        for (int j = 0; j < 4; j++)
#pragma unroll
            for (int q = 0; q < 4; q++) acc[i][j][q] = 0.f;

    const int nt = Kdim / BKT;

    auto stage = [&](int t, int st) {
        const int k = t * BKT + sk;
        uint32_t da = saA + (uint32_t)(st * STAGE_F + sk * AMS + sm8) * 4u;
        const float* ga = A + (((size_t)bq * C + k) << 10) + p0 + sm8;
        cp16(da, ga);
        cp16(da + 16, ga + 4);
        uint32_t db = saB + (uint32_t)(st * STAGE_F + sk * AMS + sm8) * 4u;
        const float* gb = Bw + (size_t)k * Ndim + n0 + sm8;
        cp16(db, gb);
        cp16(db + 16, gb + 4);
    };

    stage(0, 0); cp_commit();
    stage(1, 1); cp_commit();

    for (int t = 0; t < nt; t++) {
        const int cur = t % 3;
        cp_wait<1>();
        __syncthreads();
        if (t + 2 < nt) stage(t + 2, (t + 2) % 3);
        cp_commit();

        const float* fA = sA + cur * STAGE_F;
        const float* fB = sB + cur * STAGE_F;
#pragma unroll
        for (int ks = 0; ks < 2; ks++) {
            const int kc = ks * 8 + (lane & 3);
            unsigned af[4][4], bf[4][2];
#pragma unroll
            for (int mi = 0; mi < 4; mi++) {
                int ar = wm * 64 + mi * 16 + (lane >> 2);
                af[mi][0] = __float_as_uint(fA[kc * AMS + ar]);
                af[mi][1] = __float_as_uint(fA[kc * AMS + ar + 8]);
                af[mi][2] = __float_as_uint(fA[(kc + 4) * AMS + ar]);
                af[mi][3] = __float_as_uint(fA[(kc + 4) * AMS + ar + 8]);
            }
#pragma unroll
            for (int nj = 0; nj < 4; nj++) {
                int br = wn * 32 + nj * 8 + (lane >> 2);
                bf[nj][0] = __float_as_uint(fB[kc * AMS + br]);
                bf[nj][1] = __float_as_uint(fB[(kc + 4) * AMS + br]);
            }
#pragma unroll
            for (int mi = 0; mi < 4; mi++)
#pragma unroll
                for (int nj = 0; nj < 4; nj++)
                    mma_tf32(acc[mi][nj], af[mi], bf[nj]);
        }
    }

    float sg = 0.f;
    if (EPI == 2) sg = 1.f / (1.f + __expf(-gp[0]));
#pragma unroll
    for (int mi = 0; mi < 4; mi++) {
#pragma unroll
        for (int half = 0; half < 2; half++) {
            int m = m0 + wm * 64 + mi * 16 + (lane >> 2) + half * 8;
            int mb = m >> 10, p = m & 1023;
#pragma unroll
            for (int nj = 0; nj < 4; nj++) {
                int n = n0 + wn * 32 + nj * 8 + 2 * (lane & 3);
                float v0 = acc[mi][nj][half * 2 + 0] + bias[n];
                float v1 = acc[mi][nj][half * 2 + 1] + bias[n + 1];
                size_t addr = (((size_t)mb * Ndim + n) << 10) + p;
                if (EPI == 2) {
                    float c0 = convres[addr], c1 = convres[addr + 1024];
                    float r0 = resid[addr],   r1 = resid[addr + 1024];
                    v0 = fmaxf(c0 + sg * v0 + r0, 0.f);
                    v1 = fmaxf(c1 + sg * v1 + r1, 0.f);
                }
                if (ROUND) { v0 = to_tf32(v0); v1 = to_tf32(v1); }
                Cout[addr]        = v0;
                Cout[addr + 1024] = v1;
            }
        }
    }
}

// ---------------- conv3x3 via pre-shifted inputs: clean GEMM mainloop ------------
template<int EPI, int ROUND, int SHIFT>
__global__ void __launch_bounds__(256, 2) convgemm_k(
    const float* __restrict__ A0, const float* __restrict__ Am1,
    const float* __restrict__ Ap1,
    const float* __restrict__ Bw, const float* __restrict__ bias,
    float* __restrict__ Cout, float* __restrict__ Cm1, float* __restrict__ Cp1)
{
    extern __shared__ float dyn[];
    float* sA = dyn;
    float* sB = dyn + 3 * STAGE_F;

    const int tid  = threadIdx.x;
    const int lane = tid & 31;
    const int wid  = tid >> 5;
    const int wm   = wid & 1;
    const int wn   = wid >> 1;
    const int m0 = blockIdx.x * BM;
    const int n0 = blockIdx.y * BN;
    const int bq = m0 >> 10;
    const int p0 = m0 & 1023;

    const int sk  = tid >> 4;        // channel within 16-tile
    const int sm8 = (tid & 15) * 8;

    const uint32_t saA = (uint32_t)__cvta_generic_to_shared(sA);
    const uint32_t saB = (uint32_t)__cvta_generic_to_shared(sB);

    float acc[4][4][4];
#pragma unroll
    for (int i = 0; i < 4; i++)
#pragma unroll
        for (int j = 0; j < 4; j++)
#pragma unroll
            for (int q = 0; q < 4; q++) acc[i][j][q] = 0.f;

    const int nt = 144;   // 9 taps * 16 channel-tiles

    auto stage = [&](int t, int st) {
        const int r   = t >> 4;          // tap 0..8
        const int ct  = t & 15;          // channel tile
        const int dy  = r / 3 - 1;
        const int dxi = r % 3;           // 0: dx=-1 -> Am1   1: dx=0 -> A0   2: dx=+1 -> Ap1
        const float* Ab = (dxi == 0) ? Am1 : (dxi == 1) ? A0 : Ap1;
        const int c  = ct * 16 + sk;
        uint32_t da = saA + (uint32_t)(st * STAGE_F + sk * AMS + sm8) * 4u;
        int y = ((p0 + sm8) >> 5) + dy;
        bool ok = ((unsigned)y < 32u);
        const float* ga = ok ? (Ab + (((size_t)bq * C + c) << 10) + p0 + dy * 32 + sm8) : A0;
        cp16_pred(da, ga, ok);
        cp16_pred(da + 16, ga + 4, ok);
        uint32_t db = saB + (uint32_t)(st * STAGE_F + sk * AMS + sm8) * 4u;
        const float* gb = Bw + (size_t)(t * BKT + sk) * C + n0 + sm8;
        cp16(db, gb);
        cp16(db + 16, gb + 4);
    };

    stage(0, 0); cp_commit();
    stage(1, 1); cp_commit();

    for (int t = 0; t < nt; t++) {
        const int cur = t % 3;
        cp_wait<1>();
        __syncthreads();
        if (t + 2 < nt) stage(t + 2, (t + 2) % 3);
        cp_commit();

        const float* fA = sA + cur * STAGE_F;
        const float* fB = sB + cur * STAGE_F;
#pragma unroll
        for (int ks = 0; ks < 2; ks++) {
            const int kc = ks * 8 + (lane & 3);
            unsigned af[4][4], bf[4][2];
#pragma unroll
            for (int mi = 0; mi < 4; mi++) {
                int ar = wm * 64 + mi * 16 + (lane >> 2);
                af[mi][0] = __float_as_uint(fA[kc * AMS + ar]);
                af[mi][1] = __float_as_uint(fA[kc * AMS + ar + 8]);
                af[mi][2] = __float_as_uint(fA[(kc + 4) * AMS + ar]);
                af[mi][3] = __float_as_uint(fA[(kc + 4) * AMS + ar + 8]);
            }
#pragma unroll
            for (int nj = 0; nj < 4; nj++) {
                int br = wn * 32 + nj * 8 + (lane >> 2);
                bf[nj][0] = __float_as_uint(fB[kc * AMS + br]);
                bf[nj][1] = __float_as_uint(fB[(kc + 4) * AMS + br]);
            }
#pragma unroll
            for (int mi = 0; mi < 4; mi++)
#pragma unroll
                for (int nj = 0; nj < 4; nj++)
                    mma_tf32(acc[mi][nj], af[mi], bf[nj]);
        }
    }

#pragma unroll
    for (int mi = 0; mi < 4; mi++) {
#pragma unroll
        for (int half = 0; half < 2; half++) {
            int m = m0 + wm * 64 + mi * 16 + (lane >> 2) + half * 8;
            int mb = m >> 10, p = m & 1023;
            int xcol = p & 31;
#pragma unroll
            for (int nj = 0; nj < 4; nj++) {
                int n = n0 + wn * 32 + nj * 8 + 2 * (lane & 3);
                float v0 = acc[mi][nj][half * 2 + 0] + bias[n];
                float v1 = acc[mi][nj][half * 2 + 1] + bias[n + 1];
                size_t addr = (((size_t)mb * C + n) << 10) + p;
                if (EPI == 1) { v0 = fmaxf(v0, 0.f); v1 = fmaxf(v1, 0.f); }
                if (ROUND) { v0 = to_tf32(v0); v1 = to_tf32(v1); }
                Cout[addr]        = v0;
                Cout[addr + 1024] = v1;
                if (SHIFT) {
                    if (xcol < 31) { Cm1[addr + 1] = v0; Cm1[addr + 1024 + 1] = v1; }
                    if (xcol > 0)  { Cp1[addr - 1] = v0; Cp1[addr + 1024 - 1] = v1; }
                }
            }
        }
    }
}

// ---------------- flash attention (TF32 mma, online softmax) ----------------
// block: 128 threads / 4 warps; 64 queries (16 per warp); loop 16 key-tiles of 64.
#define KS3 68    // sK/sV row stride
#define PS3 68    // sP row stride

__global__ void __launch_bounds__(128, 4) fattn_kernel(
    const float* __restrict__ qkv, float* __restrict__ out)
{
    __shared__ float sK[32 * KS3];
    __shared__ float sV[32 * KS3];
    __shared__ float sP[4 * 16 * PS3];

    const int tid  = threadIdx.x;
    const int lane = tid & 31;
    const int w    = tid >> 5;                 // 0..3
    const int q0   = blockIdx.x * 64 + w * 16; // warp query base
    const int h    = blockIdx.y;
    const int b    = blockIdx.z;

    const float* qbase = qkv + ((size_t)b * 768 + h * HDIM) * HW;
    const float* kbase = qbase + 256 * HW;
    const float* vbase = qbase + 512 * HW;

    const int qr = lane >> 2;
    const int qc = lane & 3;
    const float scale = 0.17677669529663687f;  // 1/sqrt(32)

    // Q fragments (pre-scaled, tf32-rounded)
    unsigned aq[4][4];
#pragma unroll
    for (int ks = 0; ks < 4; ks++) {
        int dc = ks * 8 + qc;
        aq[ks][0] = __float_as_uint(to_tf32(qbase[dc * HW + q0 + qr] * scale));
        aq[ks][1] = __float_as_uint(to_tf32(qbase[dc * HW + q0 + qr + 8] * scale));
        aq[ks][2] = __float_as_uint(to_tf32(qbase[(dc + 4) * HW + q0 + qr] * scale));
        aq[ks][3] = __float_as_uint(to_tf32(qbase[(dc + 4) * HW + q0 + qr + 8] * scale));
    }

    float m0 = -1e30f, m1 = -1e30f;
    float l0 = 0.f,    l1 = 0.f;
    float cO[4][4];
#pragma unroll
    for (int nd = 0; nd < 4; nd++)
#pragma unroll
        for (int q = 0; q < 4; q++) cO[nd][q] = 0.f;

    float* myP = sP + w * 16 * PS3;

    for (int kt = 0; kt < 16; kt++) {
        __syncthreads();
        // stage K,V tiles [32 d][64 k]
        for (int i = tid; i < 512; i += 128) {
            int d = i >> 4, k4 = (i & 15) * 4;
            *(float4*)&sK[d * KS3 + k4] = *(const float4*)&kbase[d * HW + kt * 64 + k4];
            *(float4*)&sV[d * KS3 + k4] = *(const float4*)&vbase[d * HW + kt * 64 + k4];
        }
        __syncthreads();

        // S = Q K : 16q x 64k
        float cS[8][4];
#pragma unroll
        for (int nj = 0; nj < 8; nj++)
#pragma unroll
            for (int q = 0; q < 4; q++) cS[nj][q] = 0.f;
#pragma unroll
        for (int ks = 0; ks < 4; ks++) {
            int dc = ks * 8 + qc;
#pragma unroll
            for (int nj = 0; nj < 8; nj++) {
                int ncol = nj * 8 + qr;
                unsigned bf[2];
                bf[0] = __float_as_uint(sK[dc * KS3 + ncol]);
                bf[1] = __float_as_uint(sK[(dc + 4) * KS3 + ncol]);
                mma_tf32(cS[nj], aq[ks], bf);
            }
        }

        // row max over tile
        float t0 = -1e30f, t1 = -1e30f;
#pragma unroll
        for (int nj = 0; nj < 8; nj++) {
            t0 = fmaxf(t0, fmaxf(cS[nj][0], cS[nj][1]));
            t1 = fmaxf(t1, fmaxf(cS[nj][2], cS[nj][3]));
        }
        t0 = fmaxf(t0, __shfl_xor_sync(0xffffffffu, t0, 1));
        t0 = fmaxf(t0, __shfl_xor_sync(0xffffffffu, t0, 2));
        t1 = fmaxf(t1, __shfl_xor_sync(0xffffffffu, t1, 1));
        t1 = fmaxf(t1, __shfl_xor_sync(0xffffffffu, t1, 2));

        float mn0 = fmaxf(m0, t0), mn1 = fmaxf(m1, t1);
        float cor0 = fast_exp(m0 - mn0), cor1 = fast_exp(m1 - mn1);
        m0 = mn0; m1 = mn1;

        float s0 = 0.f, s1 = 0.f;
#pragma unroll
        for (int nj = 0; nj < 8; nj++) {
            float p00 = fast_exp(cS[nj][0] - m0);
            float p01 = fast_exp(cS[nj][1] - m0);
            float p10 = fast_exp(cS[nj][2] - m1);
            float p11 = fast_exp(cS[nj][3] - m1);
            s0 += p00 + p01;
            s1 += p10 + p11;
            int colp = nj * 8 + 2 * qc;
            myP[qr * PS3 + colp]           = to_tf32(p00);
            myP[qr * PS3 + colp + 1]       = to_tf32(p01);
            myP[(qr + 8) * PS3 + colp]     = to_tf32(p10);
            myP[(qr + 8) * PS3 + colp + 1] = to_tf32(p11);
        }
        s0 += __shfl_xor_sync(0xffffffffu, s0, 1);
        s0 += __shfl_xor_sync(0xffffffffu, s0, 2);
        s1 += __shfl_xor_sync(0xffffffffu, s1, 1);
        s1 += __shfl_xor_sync(0xffffffffu, s1, 2);
        l0 = l0 * cor0 + s0;
        l1 = l1 * cor1 + s1;

        // rescale O
#pragma unroll
        for (int nd = 0; nd < 4; nd++) {
            cO[nd][0] *= cor0; cO[nd][1] *= cor0;
            cO[nd][2] *= cor1; cO[nd][3] *= cor1;
        }
        __syncwarp();

        // O += P V   (P: 16q x 64k via smem relayout; V: 64k x 32d)
#pragma unroll
        for (int ksp = 0; ksp < 8; ksp++) {
            int pc = ksp * 8 + qc;
            unsigned aP[4];
            aP[0] = __float_as_uint(myP[qr * PS3 + pc]);
            aP[1] = __float_as_uint(myP[(qr + 8) * PS3 + pc]);
            aP[2] = __float_as_uint(myP[qr * PS3 + pc + 4]);
            aP[3] = __float_as_uint(myP[(qr + 8) * PS3 + pc + 4]);
#pragma unroll
            for (int nd = 0; nd < 4; nd++) {
                int dc = nd * 8 + qr;
                unsigned bf[2];
                bf[0] = __float_as_uint(sV[dc * KS3 + pc]);
                bf[1] = __float_as_uint(sV[dc * KS3 + pc + 4]);
                mma_tf32(cO[nd], aP, bf);
            }
        }
        __syncwarp();
    }

    // normalize + write (tf32-rounded, consumed by out-proj GEMM)
    float il0 = 1.f / l0, il1 = 1.f / l1;
    size_t obase = ((size_t)b * C + h * HDIM) * HW;
#pragma unroll
    for (int nd = 0; nd < 4; nd++) {
        int d = nd * 8 + 2 * qc;
        out[obase + (size_t)d * HW + q0 + qr]            = to_tf32(cO[nd][0] * il0);
        out[obase + (size_t)(d + 1) * HW + q0 + qr]      = to_tf32(cO[nd][1] * il0);
        out[obase + (size_t)d * HW + q0 + qr + 8]        = to_tf32(cO[nd][2] * il1);
        out[obase + (size_t)(d + 1) * HW + q0 + qr + 8]  = to_tf32(cO[nd][3] * il1);
    }
}

// ---------------- launch ----------------
extern "C" void kernel_launch(void* const* d_in, const int* in_sizes, int n_in,
                              void* d_out, int out_size)
{
    const float* x       = (const float*)d_in[0];
    const float* conv1_w = (const float*)d_in[1];
    const float* conv1_b = (const float*)d_in[2];
    const float* bn1_g   = (const float*)d_in[3];
    const float* bn1_b   = (const float*)d_in[4];
    const float* bn1_m   = (const float*)d_in[5];
    const float* bn1_v   = (const float*)d_in[6];
    const float* conv2_w = (const float*)d_in[7];
    const float* conv2_b = (const float*)d_in[8];
    const float* bn2_g   = (const float*)d_in[9];
    const float* bn2_b   = (const float*)d_in[10];
    const float* bn2_m   = (const float*)d_in[11];
    const float* bn2_v   = (const float*)d_in[12];
    const float* q_w     = (const float*)d_in[13];
    const float* q_b     = (const float*)d_in[14];
    const float* k_w     = (const float*)d_in[15];
    const float* k_b     = (const float*)d_in[16];
    const float* v_w     = (const float*)d_in[17];
    const float* v_b     = (const float*)d_in[18];
    const float* o_w     = (const float*)d_in[19];
    const float* o_b     = (const float*)d_in[20];
    const float* gate    = (const float*)d_in[21];
    float* out           = (float*)d_out;

    float *p_w1t, *p_w2t, *p_b1, *p_b2, *p_wqkv, *p_bqkv, *p_wot;
    float *p_t1, *p_conv, *p_qkv, *p_attn;
    float *p_xm1, *p_xp1, *p_t1m, *p_t1p;
    cudaGetSymbolAddress((void**)&p_w1t,  g_w1t);
    cudaGetSymbolAddress((void**)&p_w2t,  g_w2t);
    cudaGetSymbolAddress((void**)&p_b1,   g_b1);
    cudaGetSymbolAddress((void**)&p_b2,   g_b2);
    cudaGetSymbolAddress((void**)&p_wqkv, g_wqkv);
    cudaGetSymbolAddress((void**)&p_bqkv, g_bqkv);
    cudaGetSymbolAddress((void**)&p_wot,  g_wot);
    cudaGetSymbolAddress((void**)&p_t1,   g_t1);
    cudaGetSymbolAddress((void**)&p_conv, g_conv);
    cudaGetSymbolAddress((void**)&p_qkv,  g_qkv);
    cudaGetSymbolAddress((void**)&p_attn, g_attn);
    cudaGetSymbolAddress((void**)&p_xm1,  g_xm1);
    cudaGetSymbolAddress((void**)&p_xp1,  g_xp1);
    cudaGetSymbolAddress((void**)&p_t1m,  g_t1m);
    cudaGetSymbolAddress((void**)&p_t1p,  g_t1p);

    static cudaStream_t s_side = nullptr;
    static cudaEvent_t ev_fork = nullptr, ev_join = nullptr;
    static bool attrs_set = false;
    if (s_side == nullptr) {
        cudaStreamCreateWithFlags(&s_side, cudaStreamNonBlocking);
        cudaEventCreateWithFlags(&ev_fork, cudaEventDisableTiming);
        cudaEventCreateWithFlags(&ev_join, cudaEventDisableTiming);
    }
    if (!attrs_set) {
        cudaFuncSetAttribute(gemm_k<0, 1>, cudaFuncAttributeMaxDynamicSharedMemorySize, GEMM_SMEM);
        cudaFuncSetAttribute(gemm_k<2, 0>, cudaFuncAttributeMaxDynamicSharedMemorySize, GEMM_SMEM);
        cudaFuncSetAttribute(convgemm_k<1, 1, 1>, cudaFuncAttributeMaxDynamicSharedMemorySize, GEMM_SMEM);
        cudaFuncSetAttribute(convgemm_k<0, 0, 0>, cudaFuncAttributeMaxDynamicSharedMemorySize, GEMM_SMEM);
        attrs_set = true;
    }

    // side stream: shifted copies of x (no dependencies)
    xshift_kernel<<<(BATCH * C * HW) / 256, 256, 0, s_side>>>(x, p_xm1, p_xp1);

    // main: weight transform + BN fold
    prep_kernel<<<1024, 256>>>(conv1_w, conv1_b, bn1_g, bn1_b, bn1_m, bn1_v,
                               conv2_w, conv2_b, bn2_g, bn2_b, bn2_m, bn2_v,
                               q_w, q_b, k_w, k_b, v_w, v_b, o_w);

    // fork: conv chain on side stream (after prep)
    cudaEventRecord(ev_fork, 0);
    cudaStreamWaitEvent(s_side, ev_fork, 0);

    dim3 gConv(M_TOTAL / BM, C / BN);
    convgemm_k<1, 1, 1><<<gConv, 256, GEMM_SMEM, s_side>>>(
        x, p_xm1, p_xp1, p_w1t, p_b1, p_t1, p_t1m, p_t1p);
    convgemm_k<0, 0, 0><<<gConv, 256, GEMM_SMEM, s_side>>>(
        p_t1, p_t1m, p_t1p, p_w2t, p_b2, p_conv, nullptr, nullptr);
    cudaEventRecord(ev_join, s_side);

    // main stream: qkv -> flash attention
    dim3 gQKV(M_TOTAL / BM, 768 / BN);
    gemm_k<0, 1><<<gQKV, 256, GEMM_SMEM>>>(x, p_wqkv, p_bqkv, p_qkv, C, 768,
                                           nullptr, nullptr, nullptr);
    dim3 gAttn(HW / 64, HEADS, BATCH);
    fattn_kernel<<<gAttn, 128>>>(p_qkv, p_attn);

    // join, then fused epilogue GEMM
    cudaStreamWaitEvent(0, ev_join, 0);
    dim3 gOut(M_TOTAL / BM, C / BN);
    gemm_k<2, 0><<<gOut, 256, GEMM_SMEM>>>(p_attn, p_wot, o_b, out, C, C,
                                           p_conv, x, gate);
}

// round 12
// speedup vs baseline: 1.8796x; 1.1119x over previous
#include <cuda_runtime.h>
#include <cuda_bf16.h>
#include <cstdint>
#include <math.h>

// Problem constants
#define BATCH 16
#define C 256
#define HW 1024          // 32x32
#define HEADS 8
#define HDIM 32
#define M_TOTAL (BATCH * HW)   // 16384
#define KCONV (C * 9)          // 2304

// ---------------- scratch (static device globals; no runtime allocation) ---------
__device__ float g_w1t[KCONV * C];    // [r][c][n] bn1-folded conv1 weights (tf32)
__device__ float g_w2t[KCONV * C];
__device__ float g_b1[C];
__device__ float g_b2[C];
__device__ float g_wqkv[C * 768];     // [K=256][N=768] (q|k|v transposed, tf32)
__device__ float g_bqkv[768];
__device__ float g_wot[C * C];        // out_w transposed (tf32)
__device__ float g_t1[BATCH * C * HW];
__device__ float g_conv[BATCH * C * HW];
__device__ float g_qkv[BATCH * 768 * HW];
__device__ float g_attn[BATCH * C * HW];
// shifted copies: S_m1[q] = in[q-1], S_p1[q] = in[q+1], x-row-edge zeros
__device__ float g_xm1[BATCH * C * HW];
__device__ float g_xp1[BATCH * C * HW];
__device__ float g_t1m[BATCH * C * HW];   // edge cells never written -> stay 0
__device__ float g_t1p[BATCH * C * HW];

// ---------------- helpers ----------------
__device__ __forceinline__ float to_tf32(float x) {
    float y;
    asm("cvt.rna.tf32.f32 %0, %1;" : "=f"(y) : "f"(x));
    return y;
}

__device__ __forceinline__ void mma_tf32(float* c, const unsigned* a, const unsigned* b) {
    asm volatile(
        "mma.sync.aligned.m16n8k8.row.col.f32.tf32.tf32.f32 "
        "{%0,%1,%2,%3}, {%4,%5,%6,%7}, {%8,%9}, {%0,%1,%2,%3};\n"
        : "+f"(c[0]), "+f"(c[1]), "+f"(c[2]), "+f"(c[3])
        : "r"(a[0]), "r"(a[1]), "r"(a[2]), "r"(a[3]), "r"(b[0]), "r"(b[1]));
}

__device__ __forceinline__ void cp16(uint32_t s, const void* g) {
    asm volatile("cp.async.cg.shared.global [%0], [%1], 16;" :: "r"(s), "l"(g));
}
__device__ __forceinline__ void cp16_pred(uint32_t s, const void* g, bool ok) {
    int sz = ok ? 16 : 0;
    asm volatile("cp.async.cg.shared.global [%0], [%1], 16, %2;" :: "r"(s), "l"(g), "r"(sz));
}
__device__ __forceinline__ void cp_commit() { asm volatile("cp.async.commit_group;"); }
template<int N> __device__ __forceinline__ void cp_wait() {
    asm volatile("cp.async.wait_group %0;" :: "n"(N));
}

// fast exp on the FMA pipe. x <= 0 expected.
__device__ __forceinline__ float fast_exp(float x) {
    float t = x * 1.4426950408889634f;
    t = fmaxf(t, -126.0f);
    float fi = floorf(t);
    float f = t - fi;
    float p = fmaf(f, 0.0015041f, 0.0096181f);
    p = fmaf(f, p, 0.0555041f);
    p = fmaf(f, p, 0.2402265f);
    p = fmaf(f, p, 0.6931472f);
    p = fmaf(f, p, 1.0f);
    int e = (int)fi;
    return p * __int_as_float((e + 127) << 23);
}

// ---------------- x shift kernel ----------------
__global__ void xshift_kernel(const float* __restrict__ in,
                              float* __restrict__ om1, float* __restrict__ op1)
{
    int i = blockIdx.x * blockDim.x + threadIdx.x;
    if (i >= BATCH * C * HW) return;
    int col = i & 31;
    om1[i] = (col > 0)  ? in[i - 1] : 0.f;   // S_m1[q] = in[q-1]
    op1[i] = (col < 31) ? in[i + 1] : 0.f;   // S_p1[q] = in[q+1]
}

// ---------------- weight transform + BN fold ----------------
__global__ void prep_kernel(
    const float* __restrict__ conv1_w, const float* __restrict__ conv1_b,
    const float* __restrict__ g1, const float* __restrict__ be1,
    const float* __restrict__ m1, const float* __restrict__ v1,
    const float* __restrict__ conv2_w, const float* __restrict__ conv2_b,
    const float* __restrict__ g2, const float* __restrict__ be2,
    const float* __restrict__ m2, const float* __restrict__ v2,
    const float* __restrict__ q_w, const float* __restrict__ q_b,
    const float* __restrict__ k_w, const float* __restrict__ k_b,
    const float* __restrict__ v_w, const float* __restrict__ v_b,
    const float* __restrict__ o_w)
{
    const int W1T_N = KCONV * C;          // 589824
    const int QKV_N = C * 768;            // 196608
    const int WOT_N = C * C;              // 65536
    const int total = 2 * W1T_N + QKV_N + WOT_N + 768 + 512;
    for (int i = blockIdx.x * blockDim.x + threadIdx.x; i < total;
         i += gridDim.x * blockDim.x) {
        if (i < W1T_N) {
            int k = i >> 8, o = i & 255;       // k = r*256 + c
            int r = k >> 8, c = k & 255;
            float s = g1[o] * rsqrtf(v1[o] + 1e-5f);
            g_w1t[i] = to_tf32(conv1_w[(o * C + c) * 9 + r] * s);
        } else if (i < 2 * W1T_N) {
            int j = i - W1T_N;
            int k = j >> 8, o = j & 255;
            int r = k >> 8, c = k & 255;
            float s = g2[o] * rsqrtf(v2[o] + 1e-5f);
            g_w2t[j] = to_tf32(conv2_w[(o * C + c) * 9 + r] * s);
        } else if (i < 2 * W1T_N + QKV_N) {
            int j = i - 2 * W1T_N;
            int c = j / 768, n = j - c * 768;
            float w;
            if (n < 256)      w = q_w[n * C + c];
            else if (n < 512) w = k_w[(n - 256) * C + c];
            else              w = v_w[(n - 512) * C + c];
            g_wqkv[j] = to_tf32(w);
        } else if (i < 2 * W1T_N + QKV_N + WOT_N) {
            int j = i - (2 * W1T_N + QKV_N);
            int c = j >> 8, o = j & 255;
            g_wot[j] = to_tf32(o_w[o * C + c]);
        } else if (i < 2 * W1T_N + QKV_N + WOT_N + 768) {
            int n = i - (2 * W1T_N + QKV_N + WOT_N);
            float bb;
            if (n < 256)      bb = q_b[n];
            else if (n < 512) bb = k_b[n - 256];
            else              bb = v_b[n - 512];
            g_bqkv[n] = bb;
        } else {
            int j = i - (2 * W1T_N + QKV_N + WOT_N + 768); // 0..511
            int o = j & 255;
            if (j < 256) {
                float s = g1[o] * rsqrtf(v1[o] + 1e-5f);
                g_b1[o] = conv1_b[o] * s + be1[o] - m1[o] * s;
            } else {
                float s = g2[o] * rsqrtf(v2[o] + 1e-5f);
                g_b2[o] = conv2_b[o] * s + be2[o] - m2[o] * s;
            }
        }
    }
}

// ---------------- common tile params ----------------
#define BM 128
#define BN 128
#define BKT 16
#define AMS 136   // 136 % 32 = 8 -> conflict-free fragment LDS
#define STAGE_F (BKT * AMS)   // floats per stage per matrix = 2176
#define GEMM_SMEM ((3 * STAGE_F * 2) * 4)

// ---------------- 1x1 TF32 GEMM (qkv / out-proj), 3-stage cp.async ----------------
template<int EPI, int ROUND>
__global__ void __launch_bounds__(256, 2) gemm_k(
    const float* __restrict__ A, const float* __restrict__ Bw,
    const float* __restrict__ bias, float* __restrict__ Cout,
    int Kdim, int Ndim,
    const float* __restrict__ convres, const float* __restrict__ resid,
    const float* __restrict__ gp)
{
    extern __shared__ float dyn[];
    float* sA = dyn;
    float* sB = dyn + 3 * STAGE_F;

    const int tid  = threadIdx.x;
    const int lane = tid & 31;
    const int wid  = tid >> 5;
    const int wm   = wid & 1;
    const int wn   = wid >> 1;
    const int m0 = blockIdx.x * BM;
    const int n0 = blockIdx.y * BN;
    const int bq = m0 >> 10;
    const int p0 = m0 & 1023;

    const int sk  = tid >> 4;
    const int sm8 = (tid & 15) * 8;

    const uint32_t saA = (uint32_t)__cvta_generic_to_shared(sA);
    const uint32_t saB = (uint32_t)__cvta_generic_to_shared(sB);

    float acc[4][4][4];
#pragma unroll
    for (int i = 0; i < 4; i++)
#pragma unroll
        for (int j = 0; j < 4; j++)
#pragma unroll
            for (int q = 0; q < 4; q++) acc[i][j][q] = 0.f;

    const int nt = Kdim / BKT;

    auto stage = [&](int t, int st) {
        const int k = t * BKT + sk;
        uint32_t da = saA + (uint32_t)(st * STAGE_F + sk * AMS + sm8) * 4u;
        const float* ga = A + (((size_t)bq * C + k) << 10) + p0 + sm8;
        cp16(da, ga);
        cp16(da + 16, ga + 4);
        uint32_t db = saB + (uint32_t)(st * STAGE_F + sk * AMS + sm8) * 4u;
        const float* gb = Bw + (size_t)k * Ndim + n0 + sm8;
        cp16(db, gb);
        cp16(db + 16, gb + 4);
    };

    stage(0, 0); cp_commit();
    stage(1, 1); cp_commit();

    for (int t = 0; t < nt; t++) {
        const int cur = t % 3;
        cp_wait<1>();
        __syncthreads();
        if (t + 2 < nt) stage(t + 2, (t + 2) % 3);
        cp_commit();

        const float* fA = sA + cur * STAGE_F;
        const float* fB = sB + cur * STAGE_F;
#pragma unroll
        for (int ks = 0; ks < 2; ks++) {
            const int kc = ks * 8 + (lane & 3);
            unsigned af[4][4], bf[4][2];
#pragma unroll
            for (int mi = 0; mi < 4; mi++) {
                int ar = wm * 64 + mi * 16 + (lane >> 2);
                af[mi][0] = __float_as_uint(fA[kc * AMS + ar]);
                af[mi][1] = __float_as_uint(fA[kc * AMS + ar + 8]);
                af[mi][2] = __float_as_uint(fA[(kc + 4) * AMS + ar]);
                af[mi][3] = __float_as_uint(fA[(kc + 4) * AMS + ar + 8]);
            }
#pragma unroll
            for (int nj = 0; nj < 4; nj++) {
                int br = wn * 32 + nj * 8 + (lane >> 2);
                bf[nj][0] = __float_as_uint(fB[kc * AMS + br]);
                bf[nj][1] = __float_as_uint(fB[(kc + 4) * AMS + br]);
            }
#pragma unroll
            for (int mi = 0; mi < 4; mi++)
#pragma unroll
                for (int nj = 0; nj < 4; nj++)
                    mma_tf32(acc[mi][nj], af[mi], bf[nj]);
        }
    }

    float sg = 0.f;
    if (EPI == 2) sg = 1.f / (1.f + __expf(-gp[0]));
#pragma unroll
    for (int mi = 0; mi < 4; mi++) {
#pragma unroll
        for (int half = 0; half < 2; half++) {
            int m = m0 + wm * 64 + mi * 16 + (lane >> 2) + half * 8;
            int mb = m >> 10, p = m & 1023;
#pragma unroll
            for (int nj = 0; nj < 4; nj++) {
                int n = n0 + wn * 32 + nj * 8 + 2 * (lane & 3);
                float v0 = acc[mi][nj][half * 2 + 0] + bias[n];
                float v1 = acc[mi][nj][half * 2 + 1] + bias[n + 1];
                size_t addr = (((size_t)mb * Ndim + n) << 10) + p;
                if (EPI == 2) {
                    float c0 = convres[addr], c1 = convres[addr + 1024];
                    float r0 = resid[addr],   r1 = resid[addr + 1024];
                    v0 = fmaxf(c0 + sg * v0 + r0, 0.f);
                    v1 = fmaxf(c1 + sg * v1 + r1, 0.f);
                }
                if (ROUND) { v0 = to_tf32(v0); v1 = to_tf32(v1); }
                Cout[addr]        = v0;
                Cout[addr + 1024] = v1;
            }
        }
    }
}

// ---------------- conv3x3 via pre-shifted inputs: clean GEMM mainloop ------------
template<int EPI, int ROUND, int SHIFT>
__global__ void __launch_bounds__(256, 2) convgemm_k(
    const float* __restrict__ A0, const float* __restrict__ Am1,
    const float* __restrict__ Ap1,
    const float* __restrict__ Bw, const float* __restrict__ bias,
    float* __restrict__ Cout, float* __restrict__ Cm1, float* __restrict__ Cp1)
{
    extern __shared__ float dyn[];
    float* sA = dyn;
    float* sB = dyn + 3 * STAGE_F;

    const int tid  = threadIdx.x;
    const int lane = tid & 31;
    const int wid  = tid >> 5;
    const int wm   = wid & 1;
    const int wn   = wid >> 1;
    const int m0 = blockIdx.x * BM;
    const int n0 = blockIdx.y * BN;
    const int bq = m0 >> 10;
    const int p0 = m0 & 1023;

    const int sk  = tid >> 4;        // channel within 16-tile
    const int sm8 = (tid & 15) * 8;

    const uint32_t saA = (uint32_t)__cvta_generic_to_shared(sA);
    const uint32_t saB = (uint32_t)__cvta_generic_to_shared(sB);

    float acc[4][4][4];
#pragma unroll
    for (int i = 0; i < 4; i++)
#pragma unroll
        for (int j = 0; j < 4; j++)
#pragma unroll
            for (int q = 0; q < 4; q++) acc[i][j][q] = 0.f;

    const int nt = 144;   // 9 taps * 16 channel-tiles

    auto stage = [&](int t, int st) {
        const int r   = t >> 4;          // tap 0..8
        const int ct  = t & 15;          // channel tile
        const int dy  = r / 3 - 1;
        const int dxi = r % 3;           // 0: dx=-1 -> Am1   1: dx=0 -> A0   2: dx=+1 -> Ap1
        const float* Ab = (dxi == 0) ? Am1 : (dxi == 1) ? A0 : Ap1;
        const int c  = ct * 16 + sk;
        uint32_t da = saA + (uint32_t)(st * STAGE_F + sk * AMS + sm8) * 4u;
        int y = ((p0 + sm8) >> 5) + dy;
        bool ok = ((unsigned)y < 32u);
        const float* ga = ok ? (Ab + (((size_t)bq * C + c) << 10) + p0 + dy * 32 + sm8) : A0;
        cp16_pred(da, ga, ok);
        cp16_pred(da + 16, ga + 4, ok);
        uint32_t db = saB + (uint32_t)(st * STAGE_F + sk * AMS + sm8) * 4u;
        const float* gb = Bw + (size_t)(t * BKT + sk) * C + n0 + sm8;
        cp16(db, gb);
        cp16(db + 16, gb + 4);
    };

    stage(0, 0); cp_commit();
    stage(1, 1); cp_commit();

    for (int t = 0; t < nt; t++) {
        const int cur = t % 3;
        cp_wait<1>();
        __syncthreads();
        if (t + 2 < nt) stage(t + 2, (t + 2) % 3);
        cp_commit();

        const float* fA = sA + cur * STAGE_F;
        const float* fB = sB + cur * STAGE_F;
#pragma unroll
        for (int ks = 0; ks < 2; ks++) {
            const int kc = ks * 8 + (lane & 3);
            unsigned af[4][4], bf[4][2];
#pragma unroll
            for (int mi = 0; mi < 4; mi++) {
                int ar = wm * 64 + mi * 16 + (lane >> 2);
                af[mi][0] = __float_as_uint(fA[kc * AMS + ar]);
                af[mi][1] = __float_as_uint(fA[kc * AMS + ar + 8]);
                af[mi][2] = __float_as_uint(fA[(kc + 4) * AMS + ar]);
                af[mi][3] = __float_as_uint(fA[(kc + 4) * AMS + ar + 8]);
            }
#pragma unroll
            for (int nj = 0; nj < 4; nj++) {
                int br = wn * 32 + nj * 8 + (lane >> 2);
                bf[nj][0] = __float_as_uint(fB[kc * AMS + br]);
                bf[nj][1] = __float_as_uint(fB[(kc + 4) * AMS + br]);
            }
#pragma unroll
            for (int mi = 0; mi < 4; mi++)
#pragma unroll
                for (int nj = 0; nj < 4; nj++)
                    mma_tf32(acc[mi][nj], af[mi], bf[nj]);
        }
    }

#pragma unroll
    for (int mi = 0; mi < 4; mi++) {
#pragma unroll
        for (int half = 0; half < 2; half++) {
            int m = m0 + wm * 64 + mi * 16 + (lane >> 2) + half * 8;
            int mb = m >> 10, p = m & 1023;
            int xcol = p & 31;
#pragma unroll
            for (int nj = 0; nj < 4; nj++) {
                int n = n0 + wn * 32 + nj * 8 + 2 * (lane & 3);
                float v0 = acc[mi][nj][half * 2 + 0] + bias[n];
                float v1 = acc[mi][nj][half * 2 + 1] + bias[n + 1];
                size_t addr = (((size_t)mb * C + n) << 10) + p;
                if (EPI == 1) { v0 = fmaxf(v0, 0.f); v1 = fmaxf(v1, 0.f); }
                if (ROUND) { v0 = to_tf32(v0); v1 = to_tf32(v1); }
                Cout[addr]        = v0;
                Cout[addr + 1024] = v1;
                if (SHIFT) {
                    if (xcol < 31) { Cm1[addr + 1] = v0; Cm1[addr + 1024 + 1] = v1; }
                    if (xcol > 0)  { Cp1[addr - 1] = v0; Cp1[addr + 1024 - 1] = v1; }
                }
            }
        }
    }
}

// ---------------- flash attention (TF32 mma, cp.async double-buffered) ----------
// block: 128 threads / 4 warps; 64 queries (16 per warp); loop 16 key-tiles of 64.
#define KS3 68    // sK/sV row stride
#define PS3 68    // sP row stride
#define KV_F (32 * KS3)                   // 2176 floats per tile
#define FATTN_SMEM ((4 * KV_F + 4 * 16 * PS3) * 4)   // 2xK + 2xV + P = 52224 B

__global__ void __launch_bounds__(128, 4) fattn_kernel(
    const float* __restrict__ qkv, float* __restrict__ out)
{
    extern __shared__ float fsm[];
    float* sK = fsm;                      // [2][32][KS3]
    float* sV = fsm + 2 * KV_F;           // [2][32][KS3]
    float* sP = fsm + 4 * KV_F;           // [4][16][PS3]

    const int tid  = threadIdx.x;
    const int lane = tid & 31;
    const int w    = tid >> 5;                 // 0..3
    const int q0   = blockIdx.x * 64 + w * 16; // warp query base
    const int h    = blockIdx.y;
    const int b    = blockIdx.z;

    const float* qbase = qkv + ((size_t)b * 768 + h * HDIM) * HW;
    const float* kbase = qbase + 256 * HW;
    const float* vbase = qbase + 512 * HW;

    const uint32_t saK = (uint32_t)__cvta_generic_to_shared(sK);
    const uint32_t saV = (uint32_t)__cvta_generic_to_shared(sV);

    const int qr = lane >> 2;
    const int qc = lane & 3;
    const float scale = 0.17677669529663687f;  // 1/sqrt(32)

    // Q fragments (pre-scaled; producer already tf32-rounded)
    unsigned aq[4][4];
#pragma unroll
    for (int ks = 0; ks < 4; ks++) {
        int dc = ks * 8 + qc;
        aq[ks][0] = __float_as_uint(to_tf32(qbase[dc * HW + q0 + qr] * scale));
        aq[ks][1] = __float_as_uint(to_tf32(qbase[dc * HW + q0 + qr + 8] * scale));
        aq[ks][2] = __float_as_uint(to_tf32(qbase[(dc + 4) * HW + q0 + qr] * scale));
        aq[ks][3] = __float_as_uint(to_tf32(qbase[(dc + 4) * HW + q0 + qr + 8] * scale));
    }

    // stage lambda: tile kt -> buffer st
    auto stage = [&](int kt, int st) {
#pragma unroll
        for (int i = tid; i < 512; i += 128) {
            int d = i >> 4, k4 = (i & 15) * 4;
            uint32_t off = (uint32_t)(st * KV_F + d * KS3 + k4) * 4u;
            cp16(saK + off, &kbase[d * HW + kt * 64 + k4]);
            cp16(saV + off, &vbase[d * HW + kt * 64 + k4]);
        }
        cp_commit();
    };

    float m0 = -1e30f, m1 = -1e30f;
    float l0 = 0.f,    l1 = 0.f;
    float cO[4][4];
#pragma unroll
    for (int nd = 0; nd < 4; nd++)
#pragma unroll
        for (int q = 0; q < 4; q++) cO[nd][q] = 0.f;

    float* myP = sP + w * 16 * PS3;

    stage(0, 0);

    for (int kt = 0; kt < 16; kt++) {
        const int cur = kt & 1;
        // wait for tile kt (the only pending group), then barrier so every warp
        // has finished reading buffer cur^1 before we prefetch into it.
        cp_wait<0>();
        __syncthreads();
        if (kt + 1 < 16) stage(kt + 1, cur ^ 1);

        const float* fK = sK + cur * KV_F;
        const float* fV = sV + cur * KV_F;

        // S = Q K : 16q x 64k
        float cS[8][4];
#pragma unroll
        for (int nj = 0; nj < 8; nj++)
#pragma unroll
            for (int q = 0; q < 4; q++) cS[nj][q] = 0.f;
#pragma unroll
        for (int ks = 0; ks < 4; ks++) {
            int dc = ks * 8 + qc;
#pragma unroll
            for (int nj = 0; nj < 8; nj++) {
                int ncol = nj * 8 + qr;
                unsigned bf[2];
                bf[0] = __float_as_uint(fK[dc * KS3 + ncol]);
                bf[1] = __float_as_uint(fK[(dc + 4) * KS3 + ncol]);
                mma_tf32(cS[nj], aq[ks], bf);
            }
        }

        // row max over tile
        float t0 = -1e30f, t1 = -1e30f;
#pragma unroll
        for (int nj = 0; nj < 8; nj++) {
            t0 = fmaxf(t0, fmaxf(cS[nj][0], cS[nj][1]));
            t1 = fmaxf(t1, fmaxf(cS[nj][2], cS[nj][3]));
        }
        t0 = fmaxf(t0, __shfl_xor_sync(0xffffffffu, t0, 1));
        t0 = fmaxf(t0, __shfl_xor_sync(0xffffffffu, t0, 2));
        t1 = fmaxf(t1, __shfl_xor_sync(0xffffffffu, t1, 1));
        t1 = fmaxf(t1, __shfl_xor_sync(0xffffffffu, t1, 2));

        float mn0 = fmaxf(m0, t0), mn1 = fmaxf(m1, t1);
        float cor0 = fast_exp(m0 - mn0), cor1 = fast_exp(m1 - mn1);
        m0 = mn0; m1 = mn1;

        float s0 = 0.f, s1 = 0.f;
#pragma unroll
        for (int nj = 0; nj < 8; nj++) {
            float p00 = fast_exp(cS[nj][0] - m0);
            float p01 = fast_exp(cS[nj][1] - m0);
            float p10 = fast_exp(cS[nj][2] - m1);
            float p11 = fast_exp(cS[nj][3] - m1);
            s0 += p00 + p01;
            s1 += p10 + p11;
            int colp = nj * 8 + 2 * qc;
            myP[qr * PS3 + colp]           = to_tf32(p00);
            myP[qr * PS3 + colp + 1]       = to_tf32(p01);
            myP[(qr + 8) * PS3 + colp]     = to_tf32(p10);
            myP[(qr + 8) * PS3 + colp + 1] = to_tf32(p11);
        }
        s0 += __shfl_xor_sync(0xffffffffu, s0, 1);
        s0 += __shfl_xor_sync(0xffffffffu, s0, 2);
        s1 += __shfl_xor_sync(0xffffffffu, s1, 1);
        s1 += __shfl_xor_sync(0xffffffffu, s1, 2);
        l0 = l0 * cor0 + s0;
        l1 = l1 * cor1 + s1;

        // rescale O
#pragma unroll
        for (int nd = 0; nd < 4; nd++) {
            cO[nd][0] *= cor0; cO[nd][1] *= cor0;
            cO[nd][2] *= cor1; cO[nd][3] *= cor1;
        }
        __syncwarp();

        // O += P V   (P: 16q x 64k via smem relayout; V: 64k x 32d)
#pragma unroll
        for (int ksp = 0; ksp < 8; ksp++) {
            int pc = ksp * 8 + qc;
            unsigned aP[4];
            aP[0] = __float_as_uint(myP[qr * PS3 + pc]);
            aP[1] = __float_as_uint(myP[(qr + 8) * PS3 + pc]);
            aP[2] = __float_as_uint(myP[qr * PS3 + pc + 4]);
            aP[3] = __float_as_uint(myP[(qr + 8) * PS3 + pc + 4]);
#pragma unroll
            for (int nd = 0; nd < 4; nd++) {
                int dc = nd * 8 + qr;
                unsigned bf[2];
                bf[0] = __float_as_uint(fV[dc * KS3 + pc]);
                bf[1] = __float_as_uint(fV[dc * KS3 + pc + 4]);
                mma_tf32(cO[nd], aP, bf);
            }
        }
        __syncwarp();
    }

    // normalize + write (tf32-rounded, consumed by out-proj GEMM)
    float il0 = 1.f / l0, il1 = 1.f / l1;
    size_t obase = ((size_t)b * C + h * HDIM) * HW;
#pragma unroll
    for (int nd = 0; nd < 4; nd++) {
        int d = nd * 8 + 2 * qc;
        out[obase + (size_t)d * HW + q0 + qr]            = to_tf32(cO[nd][0] * il0);
        out[obase + (size_t)(d + 1) * HW + q0 + qr]      = to_tf32(cO[nd][1] * il0);
        out[obase + (size_t)d * HW + q0 + qr + 8]        = to_tf32(cO[nd][2] * il1);
        out[obase + (size_t)(d + 1) * HW + q0 + qr + 8]  = to_tf32(cO[nd][3] * il1);
    }
}

// ---------------- launch ----------------
extern "C" void kernel_launch(void* const* d_in, const int* in_sizes, int n_in,
                              void* d_out, int out_size)
{
    const float* x       = (const float*)d_in[0];
    const float* conv1_w = (const float*)d_in[1];
    const float* conv1_b = (const float*)d_in[2];
    const float* bn1_g   = (const float*)d_in[3];
    const float* bn1_b   = (const float*)d_in[4];
    const float* bn1_m   = (const float*)d_in[5];
    const float* bn1_v   = (const float*)d_in[6];
    const float* conv2_w = (const float*)d_in[7];
    const float* conv2_b = (const float*)d_in[8];
    const float* bn2_g   = (const float*)d_in[9];
    const float* bn2_b   = (const float*)d_in[10];
    const float* bn2_m   = (const float*)d_in[11];
    const float* bn2_v   = (const float*)d_in[12];
    const float* q_w     = (const float*)d_in[13];
    const float* q_b     = (const float*)d_in[14];
    const float* k_w     = (const float*)d_in[15];
    const float* k_b     = (const float*)d_in[16];
    const float* v_w     = (const float*)d_in[17];
    const float* v_b     = (const float*)d_in[18];
    const float* o_w     = (const float*)d_in[19];
    const float* o_b     = (const float*)d_in[20];
    const float* gate    = (const float*)d_in[21];
    float* out           = (float*)d_out;

    float *p_w1t, *p_w2t, *p_b1, *p_b2, *p_wqkv, *p_bqkv, *p_wot;
    float *p_t1, *p_conv, *p_qkv, *p_attn;
    float *p_xm1, *p_xp1, *p_t1m, *p_t1p;
    cudaGetSymbolAddress((void**)&p_w1t,  g_w1t);
    cudaGetSymbolAddress((void**)&p_w2t,  g_w2t);
    cudaGetSymbolAddress((void**)&p_b1,   g_b1);
    cudaGetSymbolAddress((void**)&p_b2,   g_b2);
    cudaGetSymbolAddress((void**)&p_wqkv, g_wqkv);
    cudaGetSymbolAddress((void**)&p_bqkv, g_bqkv);
    cudaGetSymbolAddress((void**)&p_wot,  g_wot);
    cudaGetSymbolAddress((void**)&p_t1,   g_t1);
    cudaGetSymbolAddress((void**)&p_conv, g_conv);
    cudaGetSymbolAddress((void**)&p_qkv,  g_qkv);
    cudaGetSymbolAddress((void**)&p_attn, g_attn);
    cudaGetSymbolAddress((void**)&p_xm1,  g_xm1);
    cudaGetSymbolAddress((void**)&p_xp1,  g_xp1);
    cudaGetSymbolAddress((void**)&p_t1m,  g_t1m);
    cudaGetSymbolAddress((void**)&p_t1p,  g_t1p);

    static cudaStream_t s_side = nullptr;
    static cudaEvent_t ev_fork = nullptr, ev_join = nullptr;
    static bool attrs_set = false;
    if (s_side == nullptr) {
        cudaStreamCreateWithFlags(&s_side, cudaStreamNonBlocking);
        cudaEventCreateWithFlags(&ev_fork, cudaEventDisableTiming);
        cudaEventCreateWithFlags(&ev_join, cudaEventDisableTiming);
    }
    if (!attrs_set) {
        cudaFuncSetAttribute(gemm_k<0, 1>, cudaFuncAttributeMaxDynamicSharedMemorySize, GEMM_SMEM);
        cudaFuncSetAttribute(gemm_k<2, 0>, cudaFuncAttributeMaxDynamicSharedMemorySize, GEMM_SMEM);
        cudaFuncSetAttribute(convgemm_k<1, 1, 1>, cudaFuncAttributeMaxDynamicSharedMemorySize, GEMM_SMEM);
        cudaFuncSetAttribute(convgemm_k<0, 0, 0>, cudaFuncAttributeMaxDynamicSharedMemorySize, GEMM_SMEM);
        cudaFuncSetAttribute(fattn_kernel, cudaFuncAttributeMaxDynamicSharedMemorySize, FATTN_SMEM);
        attrs_set = true;
    }

    // side stream: shifted copies of x (no dependencies)
    xshift_kernel<<<(BATCH * C * HW) / 256, 256, 0, s_side>>>(x, p_xm1, p_xp1);

    // main: weight transform + BN fold
    prep_kernel<<<1024, 256>>>(conv1_w, conv1_b, bn1_g, bn1_b, bn1_m, bn1_v,
                               conv2_w, conv2_b, bn2_g, bn2_b, bn2_m, bn2_v,
                               q_w, q_b, k_w, k_b, v_w, v_b, o_w);

    // fork: conv chain on side stream (after prep)
    cudaEventRecord(ev_fork, 0);
    cudaStreamWaitEvent(s_side, ev_fork, 0);

    dim3 gConv(M_TOTAL / BM, C / BN);
    convgemm_k<1, 1, 1><<<gConv, 256, GEMM_SMEM, s_side>>>(
        x, p_xm1, p_xp1, p_w1t, p_b1, p_t1, p_t1m, p_t1p);
    convgemm_k<0, 0, 0><<<gConv, 256, GEMM_SMEM, s_side>>>(
        p_t1, p_t1m, p_t1p, p_w2t, p_b2, p_conv, nullptr, nullptr);
    cudaEventRecord(ev_join, s_side);

    // main stream: qkv -> flash attention
    dim3 gQKV(M_TOTAL / BM, 768 / BN);
    gemm_k<0, 1><<<gQKV, 256, GEMM_SMEM>>>(x, p_wqkv, p_bqkv, p_qkv, C, 768,
                                           nullptr, nullptr, nullptr);
    dim3 gAttn(HW / 64, HEADS, BATCH);
    fattn_kernel<<<gAttn, 128, FATTN_SMEM>>>(p_qkv, p_attn);

    // join, then fused epilogue GEMM
    cudaStreamWaitEvent(0, ev_join, 0);
    dim3 gOut(M_TOTAL / BM, C / BN);
    gemm_k<2, 0><<<gOut, 256, GEMM_SMEM>>>(p_attn, p_wot, o_b, out, C, C,
                                           p_conv, x, gate);
}

// round 13
// speedup vs baseline: 1.9031x; 1.0125x over previous
#include <cuda_runtime.h>
#include <cuda_bf16.h>
#include <cstdint>
#include <math.h>

// Problem constants
#define BATCH 16
#define C 256
#define HW 1024          // 32x32
#define HEADS 8
#define HDIM 32
#define M_TOTAL (BATCH * HW)   // 16384
#define KCONV (C * 9)          // 2304

// ---------------- scratch (static device globals; no runtime allocation) ---------
__device__ float g_w1t[KCONV * C];    // [r][c][n] bn1-folded conv1 weights (tf32)
__device__ float g_w2t[KCONV * C];
__device__ float g_b1[C];
__device__ float g_b2[C];
__device__ float g_wqkv[C * 768];     // [K=256][N=768] (q|k|v transposed, tf32)
__device__ float g_bqkv[768];
__device__ float g_wot[C * C];        // out_w transposed (tf32)
__device__ float g_t1[BATCH * C * HW];
__device__ float g_conv[BATCH * C * HW];
__device__ float g_qkv[BATCH * 768 * HW];
__device__ float g_attn[BATCH * C * HW];
// shifted copies: S_m1[q] = in[q-1], S_p1[q] = in[q+1], x-row-edge zeros
__device__ float g_xm1[BATCH * C * HW];
__device__ float g_xp1[BATCH * C * HW];
__device__ float g_t1m[BATCH * C * HW];   // edge cells never written -> stay 0
__device__ float g_t1p[BATCH * C * HW];

// ---------------- helpers ----------------
__device__ __forceinline__ float to_tf32(float x) {
    float y;
    asm("cvt.rna.tf32.f32 %0, %1;" : "=f"(y) : "f"(x));
    return y;
}

__device__ __forceinline__ void mma_tf32(float* c, const unsigned* a, const unsigned* b) {
    asm volatile(
        "mma.sync.aligned.m16n8k8.row.col.f32.tf32.tf32.f32 "
        "{%0,%1,%2,%3}, {%4,%5,%6,%7}, {%8,%9}, {%0,%1,%2,%3};\n"
        : "+f"(c[0]), "+f"(c[1]), "+f"(c[2]), "+f"(c[3])
        : "r"(a[0]), "r"(a[1]), "r"(a[2]), "r"(a[3]), "r"(b[0]), "r"(b[1]));
}

__device__ __forceinline__ void cp16(uint32_t s, const void* g) {
    asm volatile("cp.async.cg.shared.global [%0], [%1], 16;" :: "r"(s), "l"(g));
}
__device__ __forceinline__ void cp16_pred(uint32_t s, const void* g, bool ok) {
    int sz = ok ? 16 : 0;
    asm volatile("cp.async.cg.shared.global [%0], [%1], 16, %2;" :: "r"(s), "l"(g), "r"(sz));
}
__device__ __forceinline__ void cp_commit() { asm volatile("cp.async.commit_group;"); }
template<int N> __device__ __forceinline__ void cp_wait() {
    asm volatile("cp.async.wait_group %0;" :: "n"(N));
}

// fast exp on the FMA pipe. x <= 0 expected.
__device__ __forceinline__ float fast_exp(float x) {
    float t = x * 1.4426950408889634f;
    t = fmaxf(t, -126.0f);
    float fi = floorf(t);
    float f = t - fi;
    float p = fmaf(f, 0.0015041f, 0.0096181f);
    p = fmaf(f, p, 0.0555041f);
    p = fmaf(f, p, 0.2402265f);
    p = fmaf(f, p, 0.6931472f);
    p = fmaf(f, p, 1.0f);
    int e = (int)fi;
    return p * __int_as_float((e + 127) << 23);
}

// ---------------- x shift kernel ----------------
__global__ void xshift_kernel(const float* __restrict__ in,
                              float* __restrict__ om1, float* __restrict__ op1)
{
    int i = blockIdx.x * blockDim.x + threadIdx.x;
    if (i >= BATCH * C * HW) return;
    int col = i & 31;
    om1[i] = (col > 0)  ? in[i - 1] : 0.f;   // S_m1[q] = in[q-1]
    op1[i] = (col < 31) ? in[i + 1] : 0.f;   // S_p1[q] = in[q+1]
}

// ---------------- weight transform + BN fold ----------------
__global__ void prep_kernel(
    const float* __restrict__ conv1_w, const float* __restrict__ conv1_b,
    const float* __restrict__ g1, const float* __restrict__ be1,
    const float* __restrict__ m1, const float* __restrict__ v1,
    const float* __restrict__ conv2_w, const float* __restrict__ conv2_b,
    const float* __restrict__ g2, const float* __restrict__ be2,
    const float* __restrict__ m2, const float* __restrict__ v2,
    const float* __restrict__ q_w, const float* __restrict__ q_b,
    const float* __restrict__ k_w, const float* __restrict__ k_b,
    const float* __restrict__ v_w, const float* __restrict__ v_b,
    const float* __restrict__ o_w)
{
    const int W1T_N = KCONV * C;          // 589824
    const int QKV_N = C * 768;            // 196608
    const int WOT_N = C * C;              // 65536
    const int total = 2 * W1T_N + QKV_N + WOT_N + 768 + 512;
    for (int i = blockIdx.x * blockDim.x + threadIdx.x; i < total;
         i += gridDim.x * blockDim.x) {
        if (i < W1T_N) {
            int k = i >> 8, o = i & 255;       // k = r*256 + c
            int r = k >> 8, c = k & 255;
            float s = g1[o] * rsqrtf(v1[o] + 1e-5f);
            g_w1t[i] = to_tf32(conv1_w[(o * C + c) * 9 + r] * s);
        } else if (i < 2 * W1T_N) {
            int j = i - W1T_N;
            int k = j >> 8, o = j & 255;
            int r = k >> 8, c = k & 255;
            float s = g2[o] * rsqrtf(v2[o] + 1e-5f);
            g_w2t[j] = to_tf32(conv2_w[(o * C + c) * 9 + r] * s);
        } else if (i < 2 * W1T_N + QKV_N) {
            int j = i - 2 * W1T_N;
            int c = j / 768, n = j - c * 768;
            float w;
            if (n < 256)      w = q_w[n * C + c];
            else if (n < 512) w = k_w[(n - 256) * C + c];
            else              w = v_w[(n - 512) * C + c];
            g_wqkv[j] = to_tf32(w);
        } else if (i < 2 * W1T_N + QKV_N + WOT_N) {
            int j = i - (2 * W1T_N + QKV_N);
            int c = j >> 8, o = j & 255;
            g_wot[j] = to_tf32(o_w[o * C + c]);
        } else if (i < 2 * W1T_N + QKV_N + WOT_N + 768) {
            int n = i - (2 * W1T_N + QKV_N + WOT_N);
            float bb;
            if (n < 256)      bb = q_b[n];
            else if (n < 512) bb = k_b[n - 256];
            else              bb = v_b[n - 512];
            g_bqkv[n] = bb;
        } else {
            int j = i - (2 * W1T_N + QKV_N + WOT_N + 768); // 0..511
            int o = j & 255;
            if (j < 256) {
                float s = g1[o] * rsqrtf(v1[o] + 1e-5f);
                g_b1[o] = conv1_b[o] * s + be1[o] - m1[o] * s;
            } else {
                float s = g2[o] * rsqrtf(v2[o] + 1e-5f);
                g_b2[o] = conv2_b[o] * s + be2[o] - m2[o] * s;
            }
        }
    }
}

// ---------------- common tile params ----------------
#define BM 128
#define BN 128
#define BKT 32                    // 32-deep k-tile, 2-stage pipeline
#define AMS 136                   // 136 % 32 = 8 -> conflict-free fragment LDS
#define STAGE_F (BKT * AMS)       // 4352 floats per stage per matrix
#define GEMM_SMEM ((2 * STAGE_F * 2) * 4)   // 69632 B

// ---------------- 1x1 TF32 GEMM (qkv / out-proj), 2-stage cp.async ----------------
template<int EPI, int ROUND>
__global__ void __launch_bounds__(256, 2) gemm_k(
    const float* __restrict__ A, const float* __restrict__ Bw,
    const float* __restrict__ bias, float* __restrict__ Cout,
    int Kdim, int Ndim,
    const float* __restrict__ convres, const float* __restrict__ resid,
    const float* __restrict__ gp)
{
    extern __shared__ float dyn[];
    float* sA = dyn;
    float* sB = dyn + 2 * STAGE_F;

    const int tid  = threadIdx.x;
    const int lane = tid & 31;
    const int wid  = tid >> 5;
    const int wm   = wid & 1;
    const int wn   = wid >> 1;
    const int m0 = blockIdx.x * BM;
    const int n0 = blockIdx.y * BN;
    const int bq = m0 >> 10;
    const int p0 = m0 & 1023;

    const int sk  = tid >> 4;        // 0..15; rows sk and sk+16
    const int sm8 = (tid & 15) * 8;

    const uint32_t saA = (uint32_t)__cvta_generic_to_shared(sA);
    const uint32_t saB = (uint32_t)__cvta_generic_to_shared(sB);

    float acc[4][4][4];
#pragma unroll
    for (int i = 0; i < 4; i++)
#pragma unroll
        for (int j = 0; j < 4; j++)
#pragma unroll
            for (int q = 0; q < 4; q++) acc[i][j][q] = 0.f;

    const int nt = Kdim / BKT;

    auto stage = [&](int t, int st) {
#pragma unroll
        for (int r2 = 0; r2 < 2; r2++) {
            const int kr = sk + 16 * r2;
            const int k  = t * BKT + kr;
            uint32_t da = saA + (uint32_t)(st * STAGE_F + kr * AMS + sm8) * 4u;
            const float* ga = A + (((size_t)bq * C + k) << 10) + p0 + sm8;
            cp16(da, ga);
            cp16(da + 16, ga + 4);
            uint32_t db = saB + (uint32_t)(st * STAGE_F + kr * AMS + sm8) * 4u;
            const float* gb = Bw + (size_t)k * Ndim + n0 + sm8;
            cp16(db, gb);
            cp16(db + 16, gb + 4);
        }
        cp_commit();
    };

    stage(0, 0);

    for (int t = 0; t < nt; t++) {
        const int cur = t & 1;
        cp_wait<0>();
        __syncthreads();
        if (t + 1 < nt) stage(t + 1, cur ^ 1);

        const float* fA = sA + cur * STAGE_F;
        const float* fB = sB + cur * STAGE_F;
#pragma unroll
        for (int ks = 0; ks < 4; ks++) {
            const int kc = ks * 8 + (lane & 3);
            unsigned af[4][4], bf[4][2];
#pragma unroll
            for (int mi = 0; mi < 4; mi++) {
                int ar = wm * 64 + mi * 16 + (lane >> 2);
                af[mi][0] = __float_as_uint(fA[kc * AMS + ar]);
                af[mi][1] = __float_as_uint(fA[kc * AMS + ar + 8]);
                af[mi][2] = __float_as_uint(fA[(kc + 4) * AMS + ar]);
                af[mi][3] = __float_as_uint(fA[(kc + 4) * AMS + ar + 8]);
            }
#pragma unroll
            for (int nj = 0; nj < 4; nj++) {
                int br = wn * 32 + nj * 8 + (lane >> 2);
                bf[nj][0] = __float_as_uint(fB[kc * AMS + br]);
                bf[nj][1] = __float_as_uint(fB[(kc + 4) * AMS + br]);
            }
#pragma unroll
            for (int mi = 0; mi < 4; mi++)
#pragma unroll
                for (int nj = 0; nj < 4; nj++)
                    mma_tf32(acc[mi][nj], af[mi], bf[nj]);
        }
    }

    float sg = 0.f;
    if (EPI == 2) sg = 1.f / (1.f + __expf(-gp[0]));
#pragma unroll
    for (int mi = 0; mi < 4; mi++) {
#pragma unroll
        for (int half = 0; half < 2; half++) {
            int m = m0 + wm * 64 + mi * 16 + (lane >> 2) + half * 8;
            int mb = m >> 10, p = m & 1023;
#pragma unroll
            for (int nj = 0; nj < 4; nj++) {
                int n = n0 + wn * 32 + nj * 8 + 2 * (lane & 3);
                float v0 = acc[mi][nj][half * 2 + 0] + bias[n];
                float v1 = acc[mi][nj][half * 2 + 1] + bias[n + 1];
                size_t addr = (((size_t)mb * Ndim + n) << 10) + p;
                if (EPI == 2) {
                    float c0 = convres[addr], c1 = convres[addr + 1024];
                    float r0 = resid[addr],   r1 = resid[addr + 1024];
                    v0 = fmaxf(c0 + sg * v0 + r0, 0.f);
                    v1 = fmaxf(c1 + sg * v1 + r1, 0.f);
                }
                if (ROUND) { v0 = to_tf32(v0); v1 = to_tf32(v1); }
                Cout[addr]        = v0;
                Cout[addr + 1024] = v1;
            }
        }
    }
}

// ---------------- conv3x3 via pre-shifted inputs, 2-stage BKT=32 ----------------
// t = tap*8 + channel-tile(32ch); nt = 72
template<int EPI, int ROUND, int SHIFT>
__global__ void __launch_bounds__(256, 2) convgemm_k(
    const float* __restrict__ A0, const float* __restrict__ Am1,
    const float* __restrict__ Ap1,
    const float* __restrict__ Bw, const float* __restrict__ bias,
    float* __restrict__ Cout, float* __restrict__ Cm1, float* __restrict__ Cp1)
{
    extern __shared__ float dyn[];
    float* sA = dyn;
    float* sB = dyn + 2 * STAGE_F;

    const int tid  = threadIdx.x;
    const int lane = tid & 31;
    const int wid  = tid >> 5;
    const int wm   = wid & 1;
    const int wn   = wid >> 1;
    const int m0 = blockIdx.x * BM;
    const int n0 = blockIdx.y * BN;
    const int bq = m0 >> 10;
    const int p0 = m0 & 1023;

    const int sk  = tid >> 4;        // 0..15; rows sk and sk+16
    const int sm8 = (tid & 15) * 8;

    const uint32_t saA = (uint32_t)__cvta_generic_to_shared(sA);
    const uint32_t saB = (uint32_t)__cvta_generic_to_shared(sB);

    float acc[4][4][4];
#pragma unroll
    for (int i = 0; i < 4; i++)
#pragma unroll
        for (int j = 0; j < 4; j++)
#pragma unroll
            for (int q = 0; q < 4; q++) acc[i][j][q] = 0.f;

    const int nt = 72;   // 9 taps * 8 channel-tiles of 32

    auto stage = [&](int t, int st) {
        const int r   = t >> 3;          // tap 0..8
        const int ct  = t & 7;           // channel tile (32 ch)
        const int dy  = r / 3 - 1;
        const int dxi = r % 3;           // 0: dx=-1 -> Am1   1: dx=0 -> A0   2: dx=+1 -> Ap1
        const float* Ab = (dxi == 0) ? Am1 : (dxi == 1) ? A0 : Ap1;
        int y = ((p0 + sm8) >> 5) + dy;
        bool ok = ((unsigned)y < 32u);
#pragma unroll
        for (int r2 = 0; r2 < 2; r2++) {
            const int kr = sk + 16 * r2;
            const int c  = ct * 32 + kr;
            uint32_t da = saA + (uint32_t)(st * STAGE_F + kr * AMS + sm8) * 4u;
            const float* ga = ok ? (Ab + (((size_t)bq * C + c) << 10) + p0 + dy * 32 + sm8) : A0;
            cp16_pred(da, ga, ok);
            cp16_pred(da + 16, ga + 4, ok);
            uint32_t db = saB + (uint32_t)(st * STAGE_F + kr * AMS + sm8) * 4u;
            const float* gb = Bw + (size_t)(t * BKT + kr) * C + n0 + sm8;
            cp16(db, gb);
            cp16(db + 16, gb + 4);
        }
        cp_commit();
    };

    stage(0, 0);

    for (int t = 0; t < nt; t++) {
        const int cur = t & 1;
        cp_wait<0>();
        __syncthreads();
        if (t + 1 < nt) stage(t + 1, cur ^ 1);

        const float* fA = sA + cur * STAGE_F;
        const float* fB = sB + cur * STAGE_F;
#pragma unroll
        for (int ks = 0; ks < 4; ks++) {
            const int kc = ks * 8 + (lane & 3);
            unsigned af[4][4], bf[4][2];
#pragma unroll
            for (int mi = 0; mi < 4; mi++) {
                int ar = wm * 64 + mi * 16 + (lane >> 2);
                af[mi][0] = __float_as_uint(fA[kc * AMS + ar]);
                af[mi][1] = __float_as_uint(fA[kc * AMS + ar + 8]);
                af[mi][2] = __float_as_uint(fA[(kc + 4) * AMS + ar]);
                af[mi][3] = __float_as_uint(fA[(kc + 4) * AMS + ar + 8]);
            }
#pragma unroll
            for (int nj = 0; nj < 4; nj++) {
                int br = wn * 32 + nj * 8 + (lane >> 2);
                bf[nj][0] = __float_as_uint(fB[kc * AMS + br]);
                bf[nj][1] = __float_as_uint(fB[(kc + 4) * AMS + br]);
            }
#pragma unroll
            for (int mi = 0; mi < 4; mi++)
#pragma unroll
                for (int nj = 0; nj < 4; nj++)
                    mma_tf32(acc[mi][nj], af[mi], bf[nj]);
        }
    }

#pragma unroll
    for (int mi = 0; mi < 4; mi++) {
#pragma unroll
        for (int half = 0; half < 2; half++) {
            int m = m0 + wm * 64 + mi * 16 + (lane >> 2) + half * 8;
            int mb = m >> 10, p = m & 1023;
            int xcol = p & 31;
#pragma unroll
            for (int nj = 0; nj < 4; nj++) {
                int n = n0 + wn * 32 + nj * 8 + 2 * (lane & 3);
                float v0 = acc[mi][nj][half * 2 + 0] + bias[n];
                float v1 = acc[mi][nj][half * 2 + 1] + bias[n + 1];
                size_t addr = (((size_t)mb * C + n) << 10) + p;
                if (EPI == 1) { v0 = fmaxf(v0, 0.f); v1 = fmaxf(v1, 0.f); }
                if (ROUND) { v0 = to_tf32(v0); v1 = to_tf32(v1); }
                Cout[addr]        = v0;
                Cout[addr + 1024] = v1;
                if (SHIFT) {
                    if (xcol < 31) { Cm1[addr + 1] = v0; Cm1[addr + 1024 + 1] = v1; }
                    if (xcol > 0)  { Cp1[addr - 1] = v0; Cp1[addr + 1024 - 1] = v1; }
                }
            }
        }
    }
}

// ---------------- flash attention (TF32 mma, cp.async double-buffered) ----------
// block: 128 threads / 4 warps; 64 queries (16 per warp); loop 16 key-tiles of 64.
#define KS3 68    // sK/sV row stride
#define PS3 68    // sP row stride
#define KV_F (32 * KS3)                   // 2176 floats per tile
#define FATTN_SMEM ((4 * KV_F + 4 * 16 * PS3) * 4)   // 2xK + 2xV + P = 52224 B

__global__ void __launch_bounds__(128, 4) fattn_kernel(
    const float* __restrict__ qkv, float* __restrict__ out)
{
    extern __shared__ float fsm[];
    float* sK = fsm;                      // [2][32][KS3]
    float* sV = fsm + 2 * KV_F;           // [2][32][KS3]
    float* sP = fsm + 4 * KV_F;           // [4][16][PS3]

    const int tid  = threadIdx.x;
    const int lane = tid & 31;
    const int w    = tid >> 5;                 // 0..3
    const int q0   = blockIdx.x * 64 + w * 16; // warp query base
    const int h    = blockIdx.y;
    const int b    = blockIdx.z;

    const float* qbase = qkv + ((size_t)b * 768 + h * HDIM) * HW;
    const float* kbase = qbase + 256 * HW;
    const float* vbase = qbase + 512 * HW;

    const uint32_t saK = (uint32_t)__cvta_generic_to_shared(sK);
    const uint32_t saV = (uint32_t)__cvta_generic_to_shared(sV);

    const int qr = lane >> 2;
    const int qc = lane & 3;
    const float scale = 0.17677669529663687f;  // 1/sqrt(32)

    // Q fragments (pre-scaled; producer already tf32-rounded)
    unsigned aq[4][4];
#pragma unroll
    for (int ks = 0; ks < 4; ks++) {
        int dc = ks * 8 + qc;
        aq[ks][0] = __float_as_uint(to_tf32(qbase[dc * HW + q0 + qr] * scale));
        aq[ks][1] = __float_as_uint(to_tf32(qbase[dc * HW + q0 + qr + 8] * scale));
        aq[ks][2] = __float_as_uint(to_tf32(qbase[(dc + 4) * HW + q0 + qr] * scale));
        aq[ks][3] = __float_as_uint(to_tf32(qbase[(dc + 4) * HW + q0 + qr + 8] * scale));
    }

    // stage lambda: tile kt -> buffer st
    auto stage = [&](int kt, int st) {
#pragma unroll
        for (int i = tid; i < 512; i += 128) {
            int d = i >> 4, k4 = (i & 15) * 4;
            uint32_t off = (uint32_t)(st * KV_F + d * KS3 + k4) * 4u;
            cp16(saK + off, &kbase[d * HW + kt * 64 + k4]);
            cp16(saV + off, &vbase[d * HW + kt * 64 + k4]);
        }
        cp_commit();
    };

    float m0 = -1e30f, m1 = -1e30f;
    float l0 = 0.f,    l1 = 0.f;
    float cO[4][4];
#pragma unroll
    for (int nd = 0; nd < 4; nd++)
#pragma unroll
        for (int q = 0; q < 4; q++) cO[nd][q] = 0.f;

    float* myP = sP + w * 16 * PS3;

    stage(0, 0);

    for (int kt = 0; kt < 16; kt++) {
        const int cur = kt & 1;
        cp_wait<0>();
        __syncthreads();
        if (kt + 1 < 16) stage(kt + 1, cur ^ 1);

        const float* fK = sK + cur * KV_F;
        const float* fV = sV + cur * KV_F;

        // S = Q K : 16q x 64k
        float cS[8][4];
#pragma unroll
        for (int nj = 0; nj < 8; nj++)
#pragma unroll
            for (int q = 0; q < 4; q++) cS[nj][q] = 0.f;
#pragma unroll
        for (int ks = 0; ks < 4; ks++) {
            int dc = ks * 8 + qc;
#pragma unroll
            for (int nj = 0; nj < 8; nj++) {
                int ncol = nj * 8 + qr;
                unsigned bf[2];
                bf[0] = __float_as_uint(fK[dc * KS3 + ncol]);
                bf[1] = __float_as_uint(fK[(dc + 4) * KS3 + ncol]);
                mma_tf32(cS[nj], aq[ks], bf);
            }
        }

        // row max over tile
        float t0 = -1e30f, t1 = -1e30f;
#pragma unroll
        for (int nj = 0; nj < 8; nj++) {
            t0 = fmaxf(t0, fmaxf(cS[nj][0], cS[nj][1]));
            t1 = fmaxf(t1, fmaxf(cS[nj][2], cS[nj][3]));
        }
        t0 = fmaxf(t0, __shfl_xor_sync(0xffffffffu, t0, 1));
        t0 = fmaxf(t0, __shfl_xor_sync(0xffffffffu, t0, 2));
        t1 = fmaxf(t1, __shfl_xor_sync(0xffffffffu, t1, 1));
        t1 = fmaxf(t1, __shfl_xor_sync(0xffffffffu, t1, 2));

        float mn0 = fmaxf(m0, t0), mn1 = fmaxf(m1, t1);
        float cor0 = fast_exp(m0 - mn0), cor1 = fast_exp(m1 - mn1);
        m0 = mn0; m1 = mn1;

        float s0 = 0.f, s1 = 0.f;
#pragma unroll
        for (int nj = 0; nj < 8; nj++) {
            float p00 = fast_exp(cS[nj][0] - m0);
            float p01 = fast_exp(cS[nj][1] - m0);
            float p10 = fast_exp(cS[nj][2] - m1);
            float p11 = fast_exp(cS[nj][3] - m1);
            s0 += p00 + p01;
            s1 += p10 + p11;
            int colp = nj * 8 + 2 * qc;
            myP[qr * PS3 + colp]           = to_tf32(p00);
            myP[qr * PS3 + colp + 1]       = to_tf32(p01);
            myP[(qr + 8) * PS3 + colp]     = to_tf32(p10);
            myP[(qr + 8) * PS3 + colp + 1] = to_tf32(p11);
        }
        s0 += __shfl_xor_sync(0xffffffffu, s0, 1);
        s0 += __shfl_xor_sync(0xffffffffu, s0, 2);
        s1 += __shfl_xor_sync(0xffffffffu, s1, 1);
        s1 += __shfl_xor_sync(0xffffffffu, s1, 2);
        l0 = l0 * cor0 + s0;
        l1 = l1 * cor1 + s1;

        // rescale O
#pragma unroll
        for (int nd = 0; nd < 4; nd++) {
            cO[nd][0] *= cor0; cO[nd][1] *= cor0;
            cO[nd][2] *= cor1; cO[nd][3] *= cor1;
        }
        __syncwarp();

        // O += P V   (P: 16q x 64k via smem relayout; V: 64k x 32d)
#pragma unroll
        for (int ksp = 0; ksp < 8; ksp++) {
            int pc = ksp * 8 + qc;
            unsigned aP[4];
            aP[0] = __float_as_uint(myP[qr * PS3 + pc]);
            aP[1] = __float_as_uint(myP[(qr + 8) * PS3 + pc]);
            aP[2] = __float_as_uint(myP[qr * PS3 + pc + 4]);
            aP[3] = __float_as_uint(myP[(qr + 8) * PS3 + pc + 4]);
#pragma unroll
            for (int nd = 0; nd < 4; nd++) {
                int dc = nd * 8 + qr;
                unsigned bf[2];
                bf[0] = __float_as_uint(fV[dc * KS3 + pc]);
                bf[1] = __float_as_uint(fV[dc * KS3 + pc + 4]);
                mma_tf32(cO[nd], aP, bf);
            }
        }
        __syncwarp();
    }

    // normalize + write (tf32-rounded, consumed by out-proj GEMM)
    float il0 = 1.f / l0, il1 = 1.f / l1;
    size_t obase = ((size_t)b * C + h * HDIM) * HW;
#pragma unroll
    for (int nd = 0; nd < 4; nd++) {
        int d = nd * 8 + 2 * qc;
        out[obase + (size_t)d * HW + q0 + qr]            = to_tf32(cO[nd][0] * il0);
        out[obase + (size_t)(d + 1) * HW + q0 + qr]      = to_tf32(cO[nd][1] * il0);
        out[obase + (size_t)d * HW + q0 + qr + 8]        = to_tf32(cO[nd][2] * il1);
        out[obase + (size_t)(d + 1) * HW + q0 + qr + 8]  = to_tf32(cO[nd][3] * il1);
    }
}

// ---------------- launch ----------------
extern "C" void kernel_launch(void* const* d_in, const int* in_sizes, int n_in,
                              void* d_out, int out_size)
{
    const float* x       = (const float*)d_in[0];
    const float* conv1_w = (const float*)d_in[1];
    const float* conv1_b = (const float*)d_in[2];
    const float* bn1_g   = (const float*)d_in[3];
    const float* bn1_b   = (const float*)d_in[4];
    const float* bn1_m   = (const float*)d_in[5];
    const float* bn1_v   = (const float*)d_in[6];
    const float* conv2_w = (const float*)d_in[7];
    const float* conv2_b = (const float*)d_in[8];
    const float* bn2_g   = (const float*)d_in[9];
    const float* bn2_b   = (const float*)d_in[10];
    const float* bn2_m   = (const float*)d_in[11];
    const float* bn2_v   = (const float*)d_in[12];
    const float* q_w     = (const float*)d_in[13];
    const float* q_b     = (const float*)d_in[14];
    const float* k_w     = (const float*)d_in[15];
    const float* k_b     = (const float*)d_in[16];
    const float* v_w     = (const float*)d_in[17];
    const float* v_b     = (const float*)d_in[18];
    const float* o_w     = (const float*)d_in[19];
    const float* o_b     = (const float*)d_in[20];
    const float* gate    = (const float*)d_in[21];
    float* out           = (float*)d_out;

    float *p_w1t, *p_w2t, *p_b1, *p_b2, *p_wqkv, *p_bqkv, *p_wot;
    float *p_t1, *p_conv, *p_qkv, *p_attn;
    float *p_xm1, *p_xp1, *p_t1m, *p_t1p;
    cudaGetSymbolAddress((void**)&p_w1t,  g_w1t);
    cudaGetSymbolAddress((void**)&p_w2t,  g_w2t);
    cudaGetSymbolAddress((void**)&p_b1,   g_b1);
    cudaGetSymbolAddress((void**)&p_b2,   g_b2);
    cudaGetSymbolAddress((void**)&p_wqkv, g_wqkv);
    cudaGetSymbolAddress((void**)&p_bqkv, g_bqkv);
    cudaGetSymbolAddress((void**)&p_wot,  g_wot);
    cudaGetSymbolAddress((void**)&p_t1,   g_t1);
    cudaGetSymbolAddress((void**)&p_conv, g_conv);
    cudaGetSymbolAddress((void**)&p_qkv,  g_qkv);
    cudaGetSymbolAddress((void**)&p_attn, g_attn);
    cudaGetSymbolAddress((void**)&p_xm1,  g_xm1);
    cudaGetSymbolAddress((void**)&p_xp1,  g_xp1);
    cudaGetSymbolAddress((void**)&p_t1m,  g_t1m);
    cudaGetSymbolAddress((void**)&p_t1p,  g_t1p);

    static cudaStream_t s_side = nullptr;
    static cudaEvent_t ev_fork = nullptr, ev_join = nullptr;
    static bool attrs_set = false;
    if (s_side == nullptr) {
        cudaStreamCreateWithFlags(&s_side, cudaStreamNonBlocking);
        cudaEventCreateWithFlags(&ev_fork, cudaEventDisableTiming);
        cudaEventCreateWithFlags(&ev_join, cudaEventDisableTiming);
    }
    if (!attrs_set) {
        cudaFuncSetAttribute(gemm_k<0, 1>, cudaFuncAttributeMaxDynamicSharedMemorySize, GEMM_SMEM);
        cudaFuncSetAttribute(gemm_k<2, 0>, cudaFuncAttributeMaxDynamicSharedMemorySize, GEMM_SMEM);
        cudaFuncSetAttribute(convgemm_k<1, 1, 1>, cudaFuncAttributeMaxDynamicSharedMemorySize, GEMM_SMEM);
        cudaFuncSetAttribute(convgemm_k<0, 0, 0>, cudaFuncAttributeMaxDynamicSharedMemorySize, GEMM_SMEM);
        cudaFuncSetAttribute(fattn_kernel, cudaFuncAttributeMaxDynamicSharedMemorySize, FATTN_SMEM);
        attrs_set = true;
    }

    // side stream: shifted copies of x (no dependencies)
    xshift_kernel<<<(BATCH * C * HW) / 256, 256, 0, s_side>>>(x, p_xm1, p_xp1);

    // main: weight transform + BN fold
    prep_kernel<<<1024, 256>>>(conv1_w, conv1_b, bn1_g, bn1_b, bn1_m, bn1_v,
                               conv2_w, conv2_b, bn2_g, bn2_b, bn2_m, bn2_v,
                               q_w, q_b, k_w, k_b, v_w, v_b, o_w);

    // fork: conv chain on side stream (after prep)
    cudaEventRecord(ev_fork, 0);
    cudaStreamWaitEvent(s_side, ev_fork, 0);

    dim3 gConv(M_TOTAL / BM, C / BN);
    convgemm_k<1, 1, 1><<<gConv, 256, GEMM_SMEM, s_side>>>(
        x, p_xm1, p_xp1, p_w1t, p_b1, p_t1, p_t1m, p_t1p);
    convgemm_k<0, 0, 0><<<gConv, 256, GEMM_SMEM, s_side>>>(
        p_t1, p_t1m, p_t1p, p_w2t, p_b2, p_conv, nullptr, nullptr);
    cudaEventRecord(ev_join, s_side);

    // main stream: qkv -> flash attention
    dim3 gQKV(M_TOTAL / BM, 768 / BN);
    gemm_k<0, 1><<<gQKV, 256, GEMM_SMEM>>>(x, p_wqkv, p_bqkv, p_qkv, C, 768,
                                           nullptr, nullptr, nullptr);
    dim3 gAttn(HW / 64, HEADS, BATCH);
    fattn_kernel<<<gAttn, 128, FATTN_SMEM>>>(p_qkv, p_attn);

    // join, then fused epilogue GEMM
    cudaStreamWaitEvent(0, ev_join, 0);
    dim3 gOut(M_TOTAL / BM, C / BN);
    gemm_k<2, 0><<<gOut, 256, GEMM_SMEM>>>(p_attn, p_wot, o_b, out, C, C,
                                           p_conv, x, gate);
}